// round 4
// baseline (speedup 1.0000x reference)
#include <cuda_runtime.h>
#include <cuda_bf16.h>
#include <cstdint>

// ---------------------------------------------------------------------------
// Problem constants
// ---------------------------------------------------------------------------
#define A_TOT 20000
#define L_TOT 80000
#define N_TOT 100000
#define E_AA  400000
#define E_AL  800000
#define ETOT  (E_AA + 2 * E_AL)
#define HDIM  64
#define BN_EPS 1e-5f

typedef unsigned long long u64;

// ---------------------------------------------------------------------------
// Scratch (device globals)
// ---------------------------------------------------------------------------
__device__ float g_x[N_TOT * HDIM];
__device__ float g_h[N_TOT * HDIM];
__device__ float g_out1[N_TOT * HDIM];
__device__ float g_deg[N_TOT];
__device__ float g_dinv[N_TOT];
__device__ float g_stats[256];
__device__ int   g_cnt[N_TOT];
__device__ int   g_rowptr[N_TOT + 1];
__device__ int   g_cursor[N_TOT];
__device__ int2  g_epack[ETOT];          // {src, nrm as float bits}, sorted by dst

// ---------------------------------------------------------------------------
// helpers
// ---------------------------------------------------------------------------
__device__ __forceinline__ float sigmoidf_(float x) {
    return 1.0f / (1.0f + __expf(-x));
}
__device__ __forceinline__ float tanhf_(float x) {
    return 2.0f / (1.0f + __expf(-2.0f * x)) - 1.0f;
}
__device__ __forceinline__ u64 ffma2(u64 a, u64 b, u64 c) {
    u64 d;
    asm("fma.rn.f32x2 %0, %1, %2, %3;" : "=l"(d) : "l"(a), "l"(b), "l"(c));
    return d;
}
__device__ __forceinline__ u64 pack2(float x, float y) {
    u64 d; asm("mov.b64 %0, {%1, %2};" : "=l"(d) : "f"(x), "f"(y)); return d;
}
__device__ __forceinline__ float2 unpack2(u64 v) {
    float2 r; asm("mov.b64 {%0, %1}, %2;" : "=f"(r.x), "=f"(r.y) : "l"(v)); return r;
}

// edge e in [0, ETOT): decode (src, dst, len) across the 3 segments
__device__ __forceinline__ void edge_decode(
    int e,
    const int* __restrict__ aa_src, const int* __restrict__ aa_dst,
    const float* __restrict__ len_aa,
    const int* __restrict__ al_a, const int* __restrict__ al_l,
    const float* __restrict__ len_al,
    int& src, int& dst, float& len)
{
    if (e < E_AA) {
        src = aa_src[e]; dst = aa_dst[e]; len = len_aa[e];
    } else if (e < E_AA + E_AL) {
        int i = e - E_AA;
        src = al_a[i]; dst = A_TOT + al_l[i]; len = len_al[i];
    } else {
        int i = e - E_AA - E_AL;
        src = A_TOT + al_l[i]; dst = al_a[i]; len = len_al[i];
    }
}

// ---------------------------------------------------------------------------
// LSTM kernel (identical to R2 — clean experiment)
// ---------------------------------------------------------------------------
template <int T, int D, bool MEAN>
__global__ __launch_bounds__(256, 1)
void lstm_kernel(const float* __restrict__ xin,
                 const float* __restrict__ Wih,
                 const float* __restrict__ Whh,
                 const float* __restrict__ bias,
                 float* __restrict__ emb_out,
                 int xnode_off, int nrows)
{
    constexpr int ROWS = 64;
    constexpr int RPW  = 8;
    constexpr int TD   = T * D;

    extern __shared__ float sm[];
    float* WhhT = sm;                     // 64*258
    float* hshD = WhhT + 64 * 258;        // 64*128
    float* WihT = hshD + ROWS * 128;      // D*256
    float* b_s  = WihT + D * 256;         // 256
    float* xs   = b_s + 256;              // ROWS*T*D

    const int tid  = threadIdx.x;
    const int base = blockIdx.x * ROWS;

    for (int idx = tid; idx < 256 * 64; idx += 256) {
        int j = idx >> 6, k = idx & 63;
        WhhT[k * 258 + j] = Whh[idx];
    }
    for (int idx = tid; idx < 256 * D; idx += 256) {
        int j = idx / D, d = idx - j * D;
        WihT[d * 256 + j] = Wih[idx];
    }
    b_s[tid] = bias[tid];
    for (int idx = tid; idx < ROWS * TD; idx += 256) {
        int r = idx / TD;
        xs[idx] = (base + r < nrows) ? xin[(size_t)base * TD + idx] : 0.0f;
    }
    for (int idx = tid; idx < ROWS * 128; idx += 256) hshD[idx] = 0.0f;
    __syncthreads();

    const int warp = tid >> 5, lane = tid & 31;
    const int r0 = warp * RPW;

    float c[RPW][2];
    float hm[RPW][2];
#pragma unroll
    for (int r = 0; r < RPW; ++r) {
        c[r][0] = c[r][1] = 0.0f;
        hm[r][0] = hm[r][1] = 0.0f;
    }

#pragma unroll 1
    for (int t = 0; t < T; ++t) {
        u64 acc[RPW][4];
        {
            u64 bb[4];
#pragma unroll
            for (int g = 0; g < 4; ++g)
                bb[g] = *(const u64*)&b_s[g * 64 + 2 * lane];
#pragma unroll
            for (int r = 0; r < RPW; ++r)
#pragma unroll
                for (int g = 0; g < 4; ++g) acc[r][g] = bb[g];
        }
#pragma unroll
        for (int d = 0; d < D; ++d) {
            u64 wv[4];
#pragma unroll
            for (int g = 0; g < 4; ++g)
                wv[g] = *(const u64*)&WihT[d * 256 + g * 64 + 2 * lane];
#pragma unroll
            for (int r = 0; r < RPW; ++r) {
                float xv = xs[(r0 + r) * TD + t * D + d];
                u64 x2 = pack2(xv, xv);
#pragma unroll
                for (int g = 0; g < 4; ++g) acc[r][g] = ffma2(wv[g], x2, acc[r][g]);
            }
        }
        if (t > 0) {
#pragma unroll 4
            for (int k = 0; k < 64; ++k) {
                u64 w0 = *(const u64*)&WhhT[k * 258 +   0 + 2 * lane];
                u64 w1 = *(const u64*)&WhhT[k * 258 +  64 + 2 * lane];
                u64 w2 = *(const u64*)&WhhT[k * 258 + 128 + 2 * lane];
                u64 w3 = *(const u64*)&WhhT[k * 258 + 192 + 2 * lane];
#pragma unroll
                for (int r = 0; r < RPW; ++r) {
                    u64 h2 = *(const u64*)&hshD[(r0 + r) * 128 + 2 * k];
                    acc[r][0] = ffma2(w0, h2, acc[r][0]);
                    acc[r][1] = ffma2(w1, h2, acc[r][1]);
                    acc[r][2] = ffma2(w2, h2, acc[r][2]);
                    acc[r][3] = ffma2(w3, h2, acc[r][3]);
                }
            }
        }
        __syncwarp();
#pragma unroll
        for (int r = 0; r < RPW; ++r) {
            float2 gi = unpack2(acc[r][0]);
            float2 gf = unpack2(acc[r][1]);
            float2 gg = unpack2(acc[r][2]);
            float2 go = unpack2(acc[r][3]);

            float i0 = sigmoidf_(gi.x), i1 = sigmoidf_(gi.y);
            float f0 = sigmoidf_(gf.x), f1 = sigmoidf_(gf.y);
            float t0 = tanhf_(gg.x),    t1 = tanhf_(gg.y);
            float o0 = sigmoidf_(go.x), o1 = sigmoidf_(go.y);

            float c0 = fmaf(f0, c[r][0], i0 * t0);
            float c1 = fmaf(f1, c[r][1], i1 * t1);
            c[r][0] = c0; c[r][1] = c1;
            float h0 = o0 * tanhf_(c0);
            float h1 = o1 * tanhf_(c1);
            if (MEAN) { hm[r][0] += h0; hm[r][1] += h1; }
            *(float4*)&hshD[(r0 + r) * 128 + 4 * lane] = make_float4(h0, h0, h1, h1);
        }
        __syncwarp();
    }

#pragma unroll
    for (int r = 0; r < RPW; ++r) {
        int row = base + r0 + r;
        if (row >= nrows) continue;
        float2 v;
        if (MEAN) {
            v.x = hm[r][0] * (1.0f / T);
            v.y = hm[r][1] * (1.0f / T);
        } else {
            v.x = hshD[(r0 + r) * 128 + 4 * lane];
            v.y = hshD[(r0 + r) * 128 + 4 * lane + 2];
        }
        *(float2*)&emb_out[(size_t)row * 64 + 2 * lane]           = v;
        *(float2*)&g_x[(size_t)(xnode_off + row) * 64 + 2 * lane] = v;
    }
}

// ---------------------------------------------------------------------------
// init: deg = 1 (self loop), cnt = 0, stats = 0
// ---------------------------------------------------------------------------
__global__ void init_kernel() {
    int i = blockIdx.x * blockDim.x + threadIdx.x;
    if (i < N_TOT) { g_deg[i] = 1.0f; g_cnt[i] = 0; }
    if (i < 256) g_stats[i] = 0.0f;
}

// ---------------------------------------------------------------------------
// histogram: per-dst count + weighted degree
// ---------------------------------------------------------------------------
__global__ void hist_kernel(const int* __restrict__ aa_src, const int* __restrict__ aa_dst,
                            const float* __restrict__ len_aa,
                            const int* __restrict__ al_a, const int* __restrict__ al_l,
                            const float* __restrict__ len_al,
                            const float* __restrict__ w_e, const float* __restrict__ b_e) {
    int e = blockIdx.x * blockDim.x + threadIdx.x;
    if (e >= ETOT) return;
    int src, dst; float len;
    edge_decode(e, aa_src, aa_dst, len_aa, al_a, al_l, len_al, src, dst, len);
    float w = sigmoidf_(fmaf(len, w_e[0], b_e[0]));
    atomicAdd(&g_deg[dst], w);
    atomicAdd(&g_cnt[dst], 1);
}

// ---------------------------------------------------------------------------
// single-block exclusive scan over g_cnt -> g_rowptr / g_cursor
// ---------------------------------------------------------------------------
__global__ __launch_bounds__(1024)
void scan_kernel() {
    __shared__ int ssum[1024];
    const int C = (N_TOT + 1023) / 1024;   // 98
    int t = threadIdx.x;
    int beg = t * C, end = min(beg + C, N_TOT);
    int s = 0;
    for (int i = beg; i < end; ++i) s += g_cnt[i];
    ssum[t] = s;
    __syncthreads();
    // Hillis-Steele inclusive scan
    for (int off = 1; off < 1024; off <<= 1) {
        int v = (t >= off) ? ssum[t - off] : 0;
        __syncthreads();
        ssum[t] += v;
        __syncthreads();
    }
    int run = ssum[t] - s;   // exclusive base
    for (int i = beg; i < end; ++i) {
        g_rowptr[i] = run;
        g_cursor[i] = run;
        run += g_cnt[i];
    }
    if (t == 1023) g_rowptr[N_TOT] = ETOT;
}

__global__ void dinv_kernel() {
    int i = blockIdx.x * blockDim.x + threadIdx.x;
    if (i >= N_TOT) return;
    float d = g_deg[i];
    g_dinv[i] = (d > 0.0f) ? rsqrtf(d) : 0.0f;
}

// ---------------------------------------------------------------------------
// scatter: place (src, final norm) records sorted by dst
// ---------------------------------------------------------------------------
__global__ void scatter_kernel(const int* __restrict__ aa_src, const int* __restrict__ aa_dst,
                               const float* __restrict__ len_aa,
                               const int* __restrict__ al_a, const int* __restrict__ al_l,
                               const float* __restrict__ len_al,
                               const float* __restrict__ w_e, const float* __restrict__ b_e) {
    int e = blockIdx.x * blockDim.x + threadIdx.x;
    if (e >= ETOT) return;
    int src, dst; float len;
    edge_decode(e, aa_src, aa_dst, len_aa, al_a, al_l, len_al, src, dst, len);
    float w = sigmoidf_(fmaf(len, w_e[0], b_e[0]));
    float nrm = g_dinv[src] * w * g_dinv[dst];
    int pos = atomicAdd(&g_cursor[dst], 1);
    g_epack[pos] = make_int2(src, __float_as_int(nrm));
}

// ---------------------------------------------------------------------------
// lin kernel: g_h = act(in) @ W
// ---------------------------------------------------------------------------
__global__ __launch_bounds__(256)
void lin_kernel(const float* __restrict__ W, int in_sel, int use_bn) {
    __shared__ float Ws[64 * 65];
    __shared__ float xsh[64 * 65];
    const float* in = in_sel ? g_out1 : g_x;

    int tid = threadIdx.x;
    for (int idx = tid; idx < 64 * 64; idx += 256) {
        int k = idx >> 6, j = idx & 63;
        Ws[k * 65 + j] = W[idx];
    }
    int base = blockIdx.x * 64;
    for (int idx = tid; idx < 64 * 64; idx += 256) {
        int r = idx >> 6, k = idx & 63;
        int row = base + r;
        float v = (row < N_TOT) ? in[(size_t)row * 64 + k] : 0.0f;
        if (use_bn) v = fmaxf(fmaf(v, g_stats[128 + k], g_stats[192 + k]), 0.0f);
        xsh[r * 65 + k] = v;
    }
    __syncthreads();

    int j = tid & 63, rl = tid >> 6;
    for (int rr = rl; rr < 64; rr += 4) {
        float a = 0.0f;
#pragma unroll
        for (int k = 0; k < 64; ++k) a = fmaf(xsh[rr * 65 + k], Ws[k * 65 + j], a);
        int row = base + rr;
        if (row < N_TOT) g_h[(size_t)row * 64 + j] = a;
    }
}

// ---------------------------------------------------------------------------
// CSR aggregation: 1 warp per dst node; no atomics; self-loop + bias fused
// ---------------------------------------------------------------------------
__global__ __launch_bounds__(256)
void agg_csr_kernel(const float* __restrict__ bvec, float* __restrict__ dout, int map) {
    int node = blockIdx.x * 8 + (threadIdx.x >> 5);
    if (node >= N_TOT) return;
    int lane = threadIdx.x & 31;

    int beg = g_rowptr[node], end = g_rowptr[node + 1];

    float ax = 0.0f, ay = 0.0f;
    int e = beg;
    for (; e + 1 < end; e += 2) {
        int2 p0 = g_epack[e];
        int2 p1 = g_epack[e + 1];
        float2 v0 = *(const float2*)&g_h[(size_t)p0.x * 64 + 2 * lane];
        float2 v1 = *(const float2*)&g_h[(size_t)p1.x * 64 + 2 * lane];
        float n0 = __int_as_float(p0.y);
        float n1 = __int_as_float(p1.y);
        ax = fmaf(v0.x, n0, ax); ay = fmaf(v0.y, n0, ay);
        ax = fmaf(v1.x, n1, ax); ay = fmaf(v1.y, n1, ay);
    }
    if (e < end) {
        int2 p0 = g_epack[e];
        float2 v0 = *(const float2*)&g_h[(size_t)p0.x * 64 + 2 * lane];
        float n0 = __int_as_float(p0.y);
        ax = fmaf(v0.x, n0, ax); ay = fmaf(v0.y, n0, ay);
    }

    // self loop (weight dinv^2) + bias
    float di = g_dinv[node];
    float dd = di * di;
    float2 hv = *(const float2*)&g_h[(size_t)node * 64 + 2 * lane];
    float2 bv = *(const float2*)&bvec[2 * lane];
    float2 res;
    res.x = fmaf(hv.x, dd, ax) + bv.x;
    res.y = fmaf(hv.y, dd, ay) + bv.y;

    float* op;
    if (map) {
        size_t off = (node < A_TOT) ? ((size_t)(A_TOT + node) * 64)
                                    : ((size_t)(A_TOT + L_TOT + node) * 64);
        op = dout + off;
    } else {
        op = g_out1 + (size_t)node * 64;
    }
    *(float2*)(op + 2 * lane) = res;
}

// ---------------------------------------------------------------------------
__global__ __launch_bounds__(256)
void bn_stats_kernel() {
    __shared__ float sh[512];
    int tid = threadIdx.x;
    int j = tid & 63;
    float s = 0.0f, s2 = 0.0f;
    for (int row = blockIdx.x * 4 + (tid >> 6); row < N_TOT; row += gridDim.x * 4) {
        float v = g_out1[(size_t)row * 64 + j];
        s += v; s2 += v * v;
    }
    sh[tid] = s; sh[256 + tid] = s2;
    __syncthreads();
    if (tid < 64) {
        float t = sh[tid] + sh[tid + 64] + sh[tid + 128] + sh[tid + 192];
        atomicAdd(&g_stats[tid], t);
    } else if (tid < 128) {
        int jj = tid - 64;
        float t = sh[256 + jj] + sh[256 + jj + 64] + sh[256 + jj + 128] + sh[256 + jj + 192];
        atomicAdd(&g_stats[64 + jj], t);
    }
}

__global__ void bn_final_kernel(const float* __restrict__ gamma, const float* __restrict__ beta) {
    int j = threadIdx.x;
    if (j >= 64) return;
    float mean = g_stats[j] * (1.0f / N_TOT);
    float var  = g_stats[64 + j] * (1.0f / N_TOT) - mean * mean;
    float rs   = rsqrtf(var + BN_EPS);
    float sc   = rs * gamma[j];
    g_stats[128 + j] = sc;
    g_stats[192 + j] = beta[j] - mean * sc;
}

// ---------------------------------------------------------------------------
extern "C" void kernel_launch(void* const* d_in, const int* in_sizes, int n_in,
                              void* d_out, int out_size) {
    const float* agent_hist = (const float*)d_in[0];
    const float* lane_nodes = (const float*)d_in[1];
    const int*   eaa        = (const int*)d_in[2];
    const float* len_aa     = (const float*)d_in[3];
    const int*   eal        = (const int*)d_in[4];
    const float* len_al     = (const float*)d_in[5];
    const float* Wih_a      = (const float*)d_in[6];
    const float* Whh_a      = (const float*)d_in[7];
    const float* b_a        = (const float*)d_in[8];
    const float* Wih_l      = (const float*)d_in[9];
    const float* Whh_l      = (const float*)d_in[10];
    const float* b_l        = (const float*)d_in[11];
    const float* w_e        = (const float*)d_in[12];
    const float* b_e        = (const float*)d_in[13];
    const float* W1         = (const float*)d_in[14];
    const float* b1         = (const float*)d_in[15];
    const float* gamma1     = (const float*)d_in[16];
    const float* beta1      = (const float*)d_in[17];
    const float* W2         = (const float*)d_in[18];
    const float* b2         = (const float*)d_in[19];
    float* out = (float*)d_out;

    const int* aa_src = eaa;
    const int* aa_dst = eaa + E_AA;
    const int* al_a   = eal;
    const int* al_l   = eal + E_AL;

    const int smem_agent = (16512 + 8192 + 256 * 5 + 256 + 64 * 20 * 5) * 4;
    const int smem_lane  = (16512 + 8192 + 256 * 2 + 256 + 64 * 10 * 2) * 4;
    cudaFuncSetAttribute((const void*)lstm_kernel<20, 5, false>,
                         cudaFuncAttributeMaxDynamicSharedMemorySize, smem_agent);
    cudaFuncSetAttribute((const void*)lstm_kernel<10, 2, true>,
                         cudaFuncAttributeMaxDynamicSharedMemorySize, smem_lane);

    // LSTMs
    lstm_kernel<20, 5, false><<<(A_TOT + 63) / 64, 256, smem_agent>>>(
        agent_hist, Wih_a, Whh_a, b_a, out, 0, A_TOT);
    lstm_kernel<10, 2, true><<<(L_TOT + 63) / 64, 256, smem_lane>>>(
        lane_nodes, Wih_l, Whh_l, b_l, out + (size_t)2 * A_TOT * 64, A_TOT, L_TOT);

    // CSR build
    init_kernel<<<(N_TOT + 255) / 256, 256>>>();
    hist_kernel<<<(ETOT + 255) / 256, 256>>>(aa_src, aa_dst, len_aa, al_a, al_l, len_al, w_e, b_e);
    scan_kernel<<<1, 1024>>>();
    dinv_kernel<<<(N_TOT + 255) / 256, 256>>>();
    scatter_kernel<<<(ETOT + 255) / 256, 256>>>(aa_src, aa_dst, len_aa, al_a, al_l, len_al, w_e, b_e);

    // conv1
    lin_kernel<<<(N_TOT + 63) / 64, 256>>>(W1, 0, 0);
    agg_csr_kernel<<<(N_TOT + 7) / 8, 256>>>(b1, out, 0);

    // BN
    bn_stats_kernel<<<512, 256>>>();
    bn_final_kernel<<<1, 64>>>(gamma1, beta1);

    // conv2 (straight into d_out regions)
    lin_kernel<<<(N_TOT + 63) / 64, 256>>>(W2, 1, 1);
    agg_csr_kernel<<<(N_TOT + 7) / 8, 256>>>(b2, out, 1);
}

// round 5
// speedup vs baseline: 1.0389x; 1.0389x over previous
#include <cuda_runtime.h>
#include <cuda_bf16.h>
#include <cstdint>

// ---------------------------------------------------------------------------
// Problem constants
// ---------------------------------------------------------------------------
#define A_TOT 20000
#define L_TOT 80000
#define N_TOT 100000
#define E_AA  400000
#define E_AL  800000
#define ETOT  (E_AA + 2 * E_AL)
#define HDIM  64
#define BN_EPS 1e-5f

typedef unsigned long long u64;

// ---------------------------------------------------------------------------
// Scratch (device globals)
// ---------------------------------------------------------------------------
__device__ float g_x[N_TOT * HDIM];
__device__ float g_h[N_TOT * HDIM];
__device__ float g_out1[N_TOT * HDIM];
__device__ float g_deg[N_TOT];
__device__ float g_dinv[N_TOT];
__device__ float g_stats[256];
__device__ int   g_cnt[N_TOT];
__device__ int   g_rowptr[N_TOT + 1];
__device__ int   g_cursor[N_TOT];
__device__ int2  g_epack[ETOT];          // {src, nrm bits}, sorted by dst

// ---------------------------------------------------------------------------
// helpers
// ---------------------------------------------------------------------------
__device__ __forceinline__ float sigmoidf_(float x) {
    return 1.0f / (1.0f + __expf(-x));
}
__device__ __forceinline__ float tanhf_(float x) {
    return 2.0f / (1.0f + __expf(-2.0f * x)) - 1.0f;
}
__device__ __forceinline__ u64 ffma2(u64 a, u64 b, u64 c) {
    u64 d;
    asm("fma.rn.f32x2 %0, %1, %2, %3;" : "=l"(d) : "l"(a), "l"(b), "l"(c));
    return d;
}
__device__ __forceinline__ u64 pack2(float x, float y) {
    u64 d; asm("mov.b64 %0, {%1, %2};" : "=l"(d) : "f"(x), "f"(y)); return d;
}
__device__ __forceinline__ float2 unpack2(u64 v) {
    float2 r; asm("mov.b64 {%0, %1}, %2;" : "=f"(r.x), "=f"(r.y) : "l"(v)); return r;
}

__device__ __forceinline__ void edge_decode(
    int e,
    const int* __restrict__ aa_src, const int* __restrict__ aa_dst,
    const float* __restrict__ len_aa,
    const int* __restrict__ al_a, const int* __restrict__ al_l,
    const float* __restrict__ len_al,
    int& src, int& dst, float& len)
{
    if (e < E_AA) {
        src = aa_src[e]; dst = aa_dst[e]; len = len_aa[e];
    } else if (e < E_AA + E_AL) {
        int i = e - E_AA;
        src = al_a[i]; dst = A_TOT + al_l[i]; len = len_al[i];
    } else {
        int i = e - E_AA - E_AL;
        src = A_TOT + al_l[i]; dst = al_a[i]; len = len_al[i];
    }
}

// ---------------------------------------------------------------------------
// LSTM kernel: 512 threads (16 warps), 128 rows/block, 8 rows/warp.
// 4 warps per SMSP for latency hiding; one shared WhhT copy per block.
//   hshD stride 132 floats (528B, 16B-aligned rows), duplicated pairs (h,h)
// ---------------------------------------------------------------------------
template <int T, int D, bool MEAN>
__global__ __launch_bounds__(512, 1)
void lstm_kernel(const float* __restrict__ xin,
                 const float* __restrict__ Wih,
                 const float* __restrict__ Whh,
                 const float* __restrict__ bias,
                 float* __restrict__ emb_out,
                 int xnode_off, int nrows)
{
    constexpr int ROWS = 128;
    constexpr int RPW  = 8;
    constexpr int TD   = T * D;
    constexpr int HS   = 132;            // hshD row stride (floats)

    extern __shared__ float sm[];
    float* WhhT = sm;                     // 64*258 = 16512
    float* hshD = WhhT + 64 * 258;        // 128*132 = 16896
    float* WihT = hshD + ROWS * HS;       // D*256
    float* b_s  = WihT + D * 256;         // 256
    float* xs   = b_s + 256;              // ROWS*T*D

    const int tid  = threadIdx.x;
    const int base = blockIdx.x * ROWS;

    for (int idx = tid; idx < 256 * 64; idx += 512) {
        int j = idx >> 6, k = idx & 63;
        WhhT[k * 258 + j] = Whh[idx];
    }
    for (int idx = tid; idx < 256 * D; idx += 512) {
        int j = idx / D, d = idx - j * D;
        WihT[d * 256 + j] = Wih[idx];
    }
    if (tid < 256) b_s[tid] = bias[tid];
    for (int idx = tid; idx < ROWS * TD; idx += 512) {
        int r = idx / TD;
        xs[idx] = (base + r < nrows) ? xin[(size_t)base * TD + idx] : 0.0f;
    }
    for (int idx = tid; idx < ROWS * HS; idx += 512) hshD[idx] = 0.0f;
    __syncthreads();

    const int warp = tid >> 5, lane = tid & 31;
    const int r0 = warp * RPW;

    float c[RPW][2];
    float hm[RPW][2];
#pragma unroll
    for (int r = 0; r < RPW; ++r) {
        c[r][0] = c[r][1] = 0.0f;
        hm[r][0] = hm[r][1] = 0.0f;
    }

#pragma unroll 1
    for (int t = 0; t < T; ++t) {
        u64 acc[RPW][4];
        {
            u64 bb[4];
#pragma unroll
            for (int g = 0; g < 4; ++g)
                bb[g] = *(const u64*)&b_s[g * 64 + 2 * lane];
#pragma unroll
            for (int r = 0; r < RPW; ++r)
#pragma unroll
                for (int g = 0; g < 4; ++g) acc[r][g] = bb[g];
        }
#pragma unroll
        for (int d = 0; d < D; ++d) {
            u64 wv[4];
#pragma unroll
            for (int g = 0; g < 4; ++g)
                wv[g] = *(const u64*)&WihT[d * 256 + g * 64 + 2 * lane];
#pragma unroll
            for (int r = 0; r < RPW; ++r) {
                float xv = xs[(r0 + r) * TD + t * D + d];
                u64 x2 = pack2(xv, xv);
#pragma unroll
                for (int g = 0; g < 4; ++g) acc[r][g] = ffma2(wv[g], x2, acc[r][g]);
            }
        }
        if (t > 0) {
#pragma unroll 4
            for (int k = 0; k < 64; ++k) {
                u64 w0 = *(const u64*)&WhhT[k * 258 +   0 + 2 * lane];
                u64 w1 = *(const u64*)&WhhT[k * 258 +  64 + 2 * lane];
                u64 w2 = *(const u64*)&WhhT[k * 258 + 128 + 2 * lane];
                u64 w3 = *(const u64*)&WhhT[k * 258 + 192 + 2 * lane];
#pragma unroll
                for (int r = 0; r < RPW; ++r) {
                    u64 h2 = *(const u64*)&hshD[(r0 + r) * HS + 2 * k];
                    acc[r][0] = ffma2(w0, h2, acc[r][0]);
                    acc[r][1] = ffma2(w1, h2, acc[r][1]);
                    acc[r][2] = ffma2(w2, h2, acc[r][2]);
                    acc[r][3] = ffma2(w3, h2, acc[r][3]);
                }
            }
        }
        __syncwarp();
#pragma unroll
        for (int r = 0; r < RPW; ++r) {
            float2 gi = unpack2(acc[r][0]);
            float2 gf = unpack2(acc[r][1]);
            float2 gg = unpack2(acc[r][2]);
            float2 go = unpack2(acc[r][3]);

            float i0 = sigmoidf_(gi.x), i1 = sigmoidf_(gi.y);
            float f0 = sigmoidf_(gf.x), f1 = sigmoidf_(gf.y);
            float t0 = tanhf_(gg.x),    t1 = tanhf_(gg.y);
            float o0 = sigmoidf_(go.x), o1 = sigmoidf_(go.y);

            float c0 = fmaf(f0, c[r][0], i0 * t0);
            float c1 = fmaf(f1, c[r][1], i1 * t1);
            c[r][0] = c0; c[r][1] = c1;
            float h0 = o0 * tanhf_(c0);
            float h1 = o1 * tanhf_(c1);
            if (MEAN) { hm[r][0] += h0; hm[r][1] += h1; }
            *(float4*)&hshD[(r0 + r) * HS + 4 * lane] = make_float4(h0, h0, h1, h1);
        }
        __syncwarp();
    }

#pragma unroll
    for (int r = 0; r < RPW; ++r) {
        int row = base + r0 + r;
        if (row >= nrows) continue;
        float2 v;
        if (MEAN) {
            v.x = hm[r][0] * (1.0f / T);
            v.y = hm[r][1] * (1.0f / T);
        } else {
            v.x = hshD[(r0 + r) * HS + 4 * lane];
            v.y = hshD[(r0 + r) * HS + 4 * lane + 2];
        }
        *(float2*)&emb_out[(size_t)row * 64 + 2 * lane]           = v;
        *(float2*)&g_x[(size_t)(xnode_off + row) * 64 + 2 * lane] = v;
    }
}

// ---------------------------------------------------------------------------
__global__ void init_kernel() {
    int i = blockIdx.x * blockDim.x + threadIdx.x;
    if (i < N_TOT) { g_deg[i] = 1.0f; g_cnt[i] = 0; }
    if (i < 256) g_stats[i] = 0.0f;
}

__global__ void hist_kernel(const int* __restrict__ aa_src, const int* __restrict__ aa_dst,
                            const float* __restrict__ len_aa,
                            const int* __restrict__ al_a, const int* __restrict__ al_l,
                            const float* __restrict__ len_al,
                            const float* __restrict__ w_e, const float* __restrict__ b_e) {
    int e = blockIdx.x * blockDim.x + threadIdx.x;
    if (e >= ETOT) return;
    int src, dst; float len;
    edge_decode(e, aa_src, aa_dst, len_aa, al_a, al_l, len_al, src, dst, len);
    float w = sigmoidf_(fmaf(len, w_e[0], b_e[0]));
    atomicAdd(&g_deg[dst], w);
    atomicAdd(&g_cnt[dst], 1);
}

__global__ __launch_bounds__(1024)
void scan_kernel() {
    __shared__ int ssum[1024];
    const int C = (N_TOT + 1023) / 1024;
    int t = threadIdx.x;
    int beg = t * C, end = min(beg + C, N_TOT);
    int s = 0;
    for (int i = beg; i < end; ++i) s += g_cnt[i];
    ssum[t] = s;
    __syncthreads();
    for (int off = 1; off < 1024; off <<= 1) {
        int v = (t >= off) ? ssum[t - off] : 0;
        __syncthreads();
        ssum[t] += v;
        __syncthreads();
    }
    int run = ssum[t] - s;
    for (int i = beg; i < end; ++i) {
        g_rowptr[i] = run;
        g_cursor[i] = run;
        run += g_cnt[i];
    }
    if (t == 1023) g_rowptr[N_TOT] = ETOT;
}

__global__ void dinv_kernel() {
    int i = blockIdx.x * blockDim.x + threadIdx.x;
    if (i >= N_TOT) return;
    float d = g_deg[i];
    g_dinv[i] = (d > 0.0f) ? rsqrtf(d) : 0.0f;
}

__global__ void scatter_kernel(const int* __restrict__ aa_src, const int* __restrict__ aa_dst,
                               const float* __restrict__ len_aa,
                               const int* __restrict__ al_a, const int* __restrict__ al_l,
                               const float* __restrict__ len_al,
                               const float* __restrict__ w_e, const float* __restrict__ b_e) {
    int e = blockIdx.x * blockDim.x + threadIdx.x;
    if (e >= ETOT) return;
    int src, dst; float len;
    edge_decode(e, aa_src, aa_dst, len_aa, al_a, al_l, len_al, src, dst, len);
    float w = sigmoidf_(fmaf(len, w_e[0], b_e[0]));
    float nrm = g_dinv[src] * w * g_dinv[dst];
    int pos = atomicAdd(&g_cursor[dst], 1);
    g_epack[pos] = make_int2(src, __float_as_int(nrm));
}

// ---------------------------------------------------------------------------
__global__ __launch_bounds__(256)
void lin_kernel(const float* __restrict__ W, int in_sel, int use_bn) {
    __shared__ float Ws[64 * 65];
    __shared__ float xsh[64 * 65];
    const float* in = in_sel ? g_out1 : g_x;

    int tid = threadIdx.x;
    for (int idx = tid; idx < 64 * 64; idx += 256) {
        int k = idx >> 6, j = idx & 63;
        Ws[k * 65 + j] = W[idx];
    }
    int base = blockIdx.x * 64;
    for (int idx = tid; idx < 64 * 64; idx += 256) {
        int r = idx >> 6, k = idx & 63;
        int row = base + r;
        float v = (row < N_TOT) ? in[(size_t)row * 64 + k] : 0.0f;
        if (use_bn) v = fmaxf(fmaf(v, g_stats[128 + k], g_stats[192 + k]), 0.0f);
        xsh[r * 65 + k] = v;
    }
    __syncthreads();

    int j = tid & 63, rl = tid >> 6;
    for (int rr = rl; rr < 64; rr += 4) {
        float a = 0.0f;
#pragma unroll
        for (int k = 0; k < 64; ++k) a = fmaf(xsh[rr * 65 + k], Ws[k * 65 + j], a);
        int row = base + rr;
        if (row < N_TOT) g_h[(size_t)row * 64 + j] = a;
    }
}

// ---------------------------------------------------------------------------
__global__ __launch_bounds__(256)
void agg_csr_kernel(const float* __restrict__ bvec, float* __restrict__ dout, int map) {
    int node = blockIdx.x * 8 + (threadIdx.x >> 5);
    if (node >= N_TOT) return;
    int lane = threadIdx.x & 31;

    int beg = g_rowptr[node], end = g_rowptr[node + 1];

    float ax = 0.0f, ay = 0.0f;
    int e = beg;
    for (; e + 1 < end; e += 2) {
        int2 p0 = g_epack[e];
        int2 p1 = g_epack[e + 1];
        float2 v0 = *(const float2*)&g_h[(size_t)p0.x * 64 + 2 * lane];
        float2 v1 = *(const float2*)&g_h[(size_t)p1.x * 64 + 2 * lane];
        float n0 = __int_as_float(p0.y);
        float n1 = __int_as_float(p1.y);
        ax = fmaf(v0.x, n0, ax); ay = fmaf(v0.y, n0, ay);
        ax = fmaf(v1.x, n1, ax); ay = fmaf(v1.y, n1, ay);
    }
    if (e < end) {
        int2 p0 = g_epack[e];
        float2 v0 = *(const float2*)&g_h[(size_t)p0.x * 64 + 2 * lane];
        float n0 = __int_as_float(p0.y);
        ax = fmaf(v0.x, n0, ax); ay = fmaf(v0.y, n0, ay);
    }

    float di = g_dinv[node];
    float dd = di * di;
    float2 hv = *(const float2*)&g_h[(size_t)node * 64 + 2 * lane];
    float2 bv = *(const float2*)&bvec[2 * lane];
    float2 res;
    res.x = fmaf(hv.x, dd, ax) + bv.x;
    res.y = fmaf(hv.y, dd, ay) + bv.y;

    float* op;
    if (map) {
        size_t off = (node < A_TOT) ? ((size_t)(A_TOT + node) * 64)
                                    : ((size_t)(A_TOT + L_TOT + node) * 64);
        op = dout + off;
    } else {
        op = g_out1 + (size_t)node * 64;
    }
    *(float2*)(op + 2 * lane) = res;
}

// ---------------------------------------------------------------------------
__global__ __launch_bounds__(256)
void bn_stats_kernel() {
    __shared__ float sh[512];
    int tid = threadIdx.x;
    int j = tid & 63;
    float s = 0.0f, s2 = 0.0f;
    for (int row = blockIdx.x * 4 + (tid >> 6); row < N_TOT; row += gridDim.x * 4) {
        float v = g_out1[(size_t)row * 64 + j];
        s += v; s2 += v * v;
    }
    sh[tid] = s; sh[256 + tid] = s2;
    __syncthreads();
    if (tid < 64) {
        float t = sh[tid] + sh[tid + 64] + sh[tid + 128] + sh[tid + 192];
        atomicAdd(&g_stats[tid], t);
    } else if (tid < 128) {
        int jj = tid - 64;
        float t = sh[256 + jj] + sh[256 + jj + 64] + sh[256 + jj + 128] + sh[256 + jj + 192];
        atomicAdd(&g_stats[64 + jj], t);
    }
}

__global__ void bn_final_kernel(const float* __restrict__ gamma, const float* __restrict__ beta) {
    int j = threadIdx.x;
    if (j >= 64) return;
    float mean = g_stats[j] * (1.0f / N_TOT);
    float var  = g_stats[64 + j] * (1.0f / N_TOT) - mean * mean;
    float rs   = rsqrtf(var + BN_EPS);
    float sc   = rs * gamma[j];
    g_stats[128 + j] = sc;
    g_stats[192 + j] = beta[j] - mean * sc;
}

// ---------------------------------------------------------------------------
extern "C" void kernel_launch(void* const* d_in, const int* in_sizes, int n_in,
                              void* d_out, int out_size) {
    const float* agent_hist = (const float*)d_in[0];
    const float* lane_nodes = (const float*)d_in[1];
    const int*   eaa        = (const int*)d_in[2];
    const float* len_aa     = (const float*)d_in[3];
    const int*   eal        = (const int*)d_in[4];
    const float* len_al     = (const float*)d_in[5];
    const float* Wih_a      = (const float*)d_in[6];
    const float* Whh_a      = (const float*)d_in[7];
    const float* b_a        = (const float*)d_in[8];
    const float* Wih_l      = (const float*)d_in[9];
    const float* Whh_l      = (const float*)d_in[10];
    const float* b_l        = (const float*)d_in[11];
    const float* w_e        = (const float*)d_in[12];
    const float* b_e        = (const float*)d_in[13];
    const float* W1         = (const float*)d_in[14];
    const float* b1         = (const float*)d_in[15];
    const float* gamma1     = (const float*)d_in[16];
    const float* beta1      = (const float*)d_in[17];
    const float* W2         = (const float*)d_in[18];
    const float* b2         = (const float*)d_in[19];
    float* out = (float*)d_out;

    const int* aa_src = eaa;
    const int* aa_dst = eaa + E_AA;
    const int* al_a   = eal;
    const int* al_l   = eal + E_AL;

    // smem: WhhT 16512 + hshD 128*132 + WihT 256D + b 256 + xs 128*T*D (floats)
    const int smem_agent = (16512 + 128 * 132 + 256 * 5 + 256 + 128 * 20 * 5) * 4; // 190,976 B
    const int smem_lane  = (16512 + 128 * 132 + 256 * 2 + 256 + 128 * 10 * 2) * 4; // 146,944 B
    cudaFuncSetAttribute((const void*)lstm_kernel<20, 5, false>,
                         cudaFuncAttributeMaxDynamicSharedMemorySize, smem_agent);
    cudaFuncSetAttribute((const void*)lstm_kernel<10, 2, true>,
                         cudaFuncAttributeMaxDynamicSharedMemorySize, smem_lane);

    // CSR build FIRST (independent of LSTM) so ncu -s 5 lands on the agent LSTM
    init_kernel<<<(N_TOT + 255) / 256, 256>>>();
    hist_kernel<<<(ETOT + 255) / 256, 256>>>(aa_src, aa_dst, len_aa, al_a, al_l, len_al, w_e, b_e);
    scan_kernel<<<1, 1024>>>();
    dinv_kernel<<<(N_TOT + 255) / 256, 256>>>();
    scatter_kernel<<<(ETOT + 255) / 256, 256>>>(aa_src, aa_dst, len_aa, al_a, al_l, len_al, w_e, b_e);

    // LSTMs (launch index 5 and 6)
    lstm_kernel<20, 5, false><<<(A_TOT + 127) / 128, 512, smem_agent>>>(
        agent_hist, Wih_a, Whh_a, b_a, out, 0, A_TOT);
    lstm_kernel<10, 2, true><<<(L_TOT + 127) / 128, 512, smem_lane>>>(
        lane_nodes, Wih_l, Whh_l, b_l, out + (size_t)2 * A_TOT * 64, A_TOT, L_TOT);

    // conv1
    lin_kernel<<<(N_TOT + 63) / 64, 256>>>(W1, 0, 0);
    agg_csr_kernel<<<(N_TOT + 7) / 8, 256>>>(b1, out, 0);

    // BN
    bn_stats_kernel<<<512, 256>>>();
    bn_final_kernel<<<1, 64>>>(gamma1, beta1);

    // conv2
    lin_kernel<<<(N_TOT + 63) / 64, 256>>>(W2, 1, 1);
    agg_csr_kernel<<<(N_TOT + 7) / 8, 256>>>(b2, out, 1);
}

// round 7
// speedup vs baseline: 1.2519x; 1.2050x over previous
#include <cuda_runtime.h>
#include <cuda_bf16.h>
#include <cstdint>

// ---------------------------------------------------------------------------
// Problem constants
// ---------------------------------------------------------------------------
#define A_TOT 20000
#define L_TOT 80000
#define N_TOT 100000
#define E_AA  400000
#define E_AL  800000
#define ETOT  (E_AA + 2 * E_AL)
#define HDIM  64
#define BN_EPS 1e-5f

typedef unsigned long long u64;

// ---------------------------------------------------------------------------
// Scratch (device globals)
// ---------------------------------------------------------------------------
__device__ float g_x[N_TOT * HDIM];
__device__ float g_h[N_TOT * HDIM];
__device__ float g_out1[N_TOT * HDIM];
__device__ float g_deg[N_TOT];
__device__ float g_dinv[N_TOT];
__device__ float g_stats[256];
__device__ int   g_cnt[N_TOT];
__device__ int   g_rowptr[N_TOT + 1];
__device__ int   g_cursor[N_TOT];
__device__ int2  g_epack[ETOT];

// ---------------------------------------------------------------------------
// math helpers
// ---------------------------------------------------------------------------
__device__ __forceinline__ float sigmoidf_(float x) {
    return 1.0f / (1.0f + __expf(-x));
}
__device__ __forceinline__ float tanhf_(float x) {
    return 2.0f / (1.0f + __expf(-2.0f * x)) - 1.0f;
}
__device__ __forceinline__ void mma_bf16(float* d, const uint32_t* a,
                                         uint32_t b0, uint32_t b1) {
    asm volatile(
        "mma.sync.aligned.m16n8k16.row.col.f32.bf16.bf16.f32 "
        "{%0,%1,%2,%3}, {%4,%5,%6,%7}, {%8,%9}, {%0,%1,%2,%3};"
        : "+f"(d[0]), "+f"(d[1]), "+f"(d[2]), "+f"(d[3])
        : "r"(a[0]), "r"(a[1]), "r"(a[2]), "r"(a[3]), "r"(b0), "r"(b1));
}
__device__ __forceinline__ uint32_t pack_bf2(float a, float b) {
    __nv_bfloat16 ha = __float2bfloat16(a), hb = __float2bfloat16(b);
    return (uint32_t)__bfloat16_as_ushort(ha) |
           ((uint32_t)__bfloat16_as_ushort(hb) << 16);
}

// ---------------------------------------------------------------------------
// LSTM via mma.sync bf16 (3-term split precision), M=64 rows/block
//   A tile [64 rows][K=208] bf16: [h_hi(64) | h_lo(64) | h_hi(64) | x(16)]
//   B tile [256 cols][K=208] bf16: [W_hi | W_hi | W_lo | Xblk]
//   stride = 132 words (528 B) -> (r*132+q) mod 32 = r*4+q : conflict-free
//   B col n (within warp slice wn): gate = nt%4, unit = wn*16+(nt/4)*8+j
// ---------------------------------------------------------------------------
#define STRW 132            // stride in 4B words
#define SM_B_OFF 33792      // A = 64*528 bytes
#define SM_XS_OFF 168960    // B = 256*528 bytes

template <int T, int D, bool MEAN>
__global__ __launch_bounds__(256, 1)
void lstm_mma_kernel(const float* __restrict__ xin,
                     const float* __restrict__ Wih,
                     const float* __restrict__ Whh,
                     const float* __restrict__ bias,
                     float* __restrict__ emb_out,
                     int xnode_off, int nrows)
{
    constexpr int TD = T * D;
    extern __shared__ char smem[];
    uint32_t* Aw = (uint32_t*)smem;
    uint32_t* Bw = (uint32_t*)(smem + SM_B_OFF);
    float*    xs = (float*)(smem + SM_XS_OFF);

    const int tid  = threadIdx.x;
    const int wid  = tid >> 5, lane = tid & 31;
    const int lrow = lane >> 2, q = lane & 3;
    const int wm = wid >> 2, wn = wid & 3;   // 2m x 4n warp grid
    const int base = blockIdx.x * 64;

    // ---- phase 1: zero A and B, load xs ----
    for (int i = tid; i < 64 * STRW; i += 256) Aw[i] = 0;
    for (int i = tid; i < 256 * STRW; i += 256) Bw[i] = 0;
    for (int idx = tid; idx < 64 * TD; idx += 256) {
        int r = idx / TD;
        xs[idx] = (base + r < nrows) ? xin[(size_t)base * TD + idx] : 0.0f;
    }
    __syncthreads();

    // ---- phase 2: fill B ----
    // Whh -> k regions 0-63 (hi), 64-127 (hi), 128-191 (lo)
    for (int idx = tid; idx < 256 * 64; idx += 256) {
        int j = idx >> 6, k = idx & 63;
        int g = j >> 6, u = j & 63;
        int n = ((u >> 4) << 6) + (((u >> 3) & 1) << 5) + (g << 3) + (u & 7);
        float w = Whh[idx];
        __nv_bfloat16 hi = __float2bfloat16(w);
        __nv_bfloat16 lo = __float2bfloat16(w - __bfloat162float(hi));
        char* bp = smem + SM_B_OFF + n * 528;
        *(__nv_bfloat16*)(bp + 2 * k)       = hi;
        *(__nv_bfloat16*)(bp + 128 + 2 * k) = hi;
        *(__nv_bfloat16*)(bp + 256 + 2 * k) = lo;
    }
    // X block: k 192..207 : [Wih_hi(D) | Wih_hi(D) | Wih_lo(D) | bias]
    {
        int j = tid;  // gate-row 0..255
        int g = j >> 6, u = j & 63;
        int n = ((u >> 4) << 6) + (((u >> 3) & 1) << 5) + (g << 3) + (u & 7);
        char* bp = smem + SM_B_OFF + n * 528 + 384;
#pragma unroll
        for (int d = 0; d < D; ++d) {
            float w = Wih[j * D + d];
            __nv_bfloat16 hi = __float2bfloat16(w);
            __nv_bfloat16 lo = __float2bfloat16(w - __bfloat162float(hi));
            *(__nv_bfloat16*)(bp + 2 * d)           = hi;
            *(__nv_bfloat16*)(bp + 2 * (D + d))     = hi;
            *(__nv_bfloat16*)(bp + 2 * (2 * D + d)) = lo;
        }
        *(__nv_bfloat16*)(bp + 2 * (3 * D)) = __float2bfloat16(bias[j]);
    }
    // A: const 1 column + x(t=0)
    if (tid < 64) {
        *(__nv_bfloat16*)(smem + tid * 528 + 384 + 2 * (3 * D)) = __float2bfloat16(1.0f);
    }
    if (tid < 192) {
        int r = tid & 63, part = tid >> 6;
        const float* xr = xs + r * TD;   // t = 0
        char* ap = smem + r * 528 + 384;
#pragma unroll
        for (int d = 0; d < D; ++d) {
            float v = xr[d];
            __nv_bfloat16 hi = __float2bfloat16(v);
            if (part == 0)      *(__nv_bfloat16*)(ap + 2 * d) = hi;
            else if (part == 1) *(__nv_bfloat16*)(ap + 2 * (D + d)) =
                                    __float2bfloat16(v - __bfloat162float(hi));
            else                *(__nv_bfloat16*)(ap + 2 * (2 * D + d)) = hi;
        }
    }
    __syncthreads();

    float cst[16], outv[16];
#pragma unroll
    for (int i = 0; i < 16; ++i) { cst[i] = 0.0f; outv[i] = 0.0f; }

#pragma unroll 1
    for (int t = 0; t < T; ++t) {
        float acc[2][8][4];
#pragma unroll
        for (int mt = 0; mt < 2; ++mt)
#pragma unroll
            for (int nt = 0; nt < 8; ++nt)
#pragma unroll
                for (int i = 0; i < 4; ++i) acc[mt][nt][i] = 0.0f;

        const int ks0 = (t == 0) ? 12 : 0;
#pragma unroll 1
        for (int ks = ks0; ks < 13; ++ks) {
            uint32_t afr[2][4];
#pragma unroll
            for (int mt = 0; mt < 2; ++mt) {
                int w0 = (wm * 32 + mt * 16 + lrow) * STRW + ks * 8 + q;
                afr[mt][0] = Aw[w0];
                afr[mt][1] = Aw[w0 + 8 * STRW];
                afr[mt][2] = Aw[w0 + 4];
                afr[mt][3] = Aw[w0 + 8 * STRW + 4];
            }
#pragma unroll
            for (int nt = 0; nt < 8; ++nt) {
                int wb = (wn * 64 + nt * 8 + lrow) * STRW + ks * 8 + q;
                uint32_t b0 = Bw[wb], b1 = Bw[wb + 4];
                mma_bf16(acc[0][nt], afr[0], b0, b1);
                mma_bf16(acc[1][nt], afr[1], b0, b1);
            }
        }
        __syncthreads();   // all A reads done

        // epilogue: each thread owns all 4 gates for its 16 (row,unit) cells
#pragma unroll
        for (int mt = 0; mt < 2; ++mt)
#pragma unroll
            for (int half = 0; half < 2; ++half)
#pragma unroll
                for (int b = 0; b < 2; ++b) {
                    float hpair[2];
#pragma unroll
                    for (int jp = 0; jp < 2; ++jp) {
                        int rg = half * 2 + jp;
                        float gi = acc[mt][b * 4 + 0][rg];
                        float gf = acc[mt][b * 4 + 1][rg];
                        float gg = acc[mt][b * 4 + 2][rg];
                        float go = acc[mt][b * 4 + 3][rg];
                        int ci = ((mt * 2 + half) * 2 + b) * 2 + jp;
                        float cn = fmaf(sigmoidf_(gf), cst[ci],
                                        sigmoidf_(gi) * tanhf_(gg));
                        cst[ci] = cn;
                        float h = sigmoidf_(go) * tanhf_(cn);
                        if (MEAN) outv[ci] += h; else outv[ci] = h;
                        hpair[jp] = h;
                    }
                    __nv_bfloat16 h0 = __float2bfloat16(hpair[0]);
                    __nv_bfloat16 h1 = __float2bfloat16(hpair[1]);
                    uint32_t hi2 = (uint32_t)__bfloat16_as_ushort(h0) |
                                   ((uint32_t)__bfloat16_as_ushort(h1) << 16);
                    uint32_t lo2 = pack_bf2(hpair[0] - __bfloat162float(h0),
                                            hpair[1] - __bfloat162float(h1));
                    int row = wm * 32 + mt * 16 + half * 8 + lrow;
                    int uw  = wn * 8 + b * 4 + q;
                    Aw[row * STRW + uw]      = hi2;   // h_hi (k region 0)
                    Aw[row * STRW + 32 + uw] = lo2;   // h_lo (k region 1)
                    Aw[row * STRW + 64 + uw] = hi2;   // h_hi (k region 2)
                }

        // fill A_x for t+1
        if (t + 1 < T && tid < 192) {
            int r = tid & 63, part = tid >> 6;
            const float* xr = xs + r * TD + (t + 1) * D;
            char* ap = smem + r * 528 + 384;
#pragma unroll
            for (int d = 0; d < D; ++d) {
                float v = xr[d];
                __nv_bfloat16 hi = __float2bfloat16(v);
                if (part == 0)      *(__nv_bfloat16*)(ap + 2 * d) = hi;
                else if (part == 1) *(__nv_bfloat16*)(ap + 2 * (D + d)) =
                                        __float2bfloat16(v - __bfloat162float(hi));
                else                *(__nv_bfloat16*)(ap + 2 * (2 * D + d)) = hi;
            }
        }
        __syncthreads();   // A writes visible for next t
    }

    // outputs: pairs (unit0, unit0+1)
    const float scale = MEAN ? (1.0f / T) : 1.0f;
#pragma unroll
    for (int mt = 0; mt < 2; ++mt)
#pragma unroll
        for (int half = 0; half < 2; ++half)
#pragma unroll
            for (int b = 0; b < 2; ++b) {
                int grow = base + wm * 32 + mt * 16 + half * 8 + lrow;
                if (grow >= nrows) continue;
                int ci0 = ((mt * 2 + half) * 2 + b) * 2;
                int unit0 = wn * 16 + b * 8 + 2 * q;
                float2 v = make_float2(outv[ci0] * scale, outv[ci0 + 1] * scale);
                *(float2*)&emb_out[(size_t)grow * 64 + unit0] = v;
                *(float2*)&g_x[(size_t)(xnode_off + grow) * 64 + unit0] = v;
            }
}

// ---------------------------------------------------------------------------
// edge decode + CSR build
// ---------------------------------------------------------------------------
__device__ __forceinline__ void edge_decode(
    int e,
    const int* __restrict__ aa_src, const int* __restrict__ aa_dst,
    const float* __restrict__ len_aa,
    const int* __restrict__ al_a, const int* __restrict__ al_l,
    const float* __restrict__ len_al,
    int& src, int& dst, float& len)
{
    if (e < E_AA) {
        src = aa_src[e]; dst = aa_dst[e]; len = len_aa[e];
    } else if (e < E_AA + E_AL) {
        int i = e - E_AA;
        src = al_a[i]; dst = A_TOT + al_l[i]; len = len_al[i];
    } else {
        int i = e - E_AA - E_AL;
        src = A_TOT + al_l[i]; dst = al_a[i]; len = len_al[i];
    }
}

__global__ void init_kernel() {
    int i = blockIdx.x * blockDim.x + threadIdx.x;
    if (i < N_TOT) { g_deg[i] = 1.0f; g_cnt[i] = 0; }
    if (i < 256) g_stats[i] = 0.0f;
}

__global__ void hist_kernel(const int* __restrict__ aa_src, const int* __restrict__ aa_dst,
                            const float* __restrict__ len_aa,
                            const int* __restrict__ al_a, const int* __restrict__ al_l,
                            const float* __restrict__ len_al,
                            const float* __restrict__ w_e, const float* __restrict__ b_e) {
    int e = blockIdx.x * blockDim.x + threadIdx.x;
    if (e >= ETOT) return;
    int src, dst; float len;
    edge_decode(e, aa_src, aa_dst, len_aa, al_a, al_l, len_al, src, dst, len);
    float w = sigmoidf_(fmaf(len, w_e[0], b_e[0]));
    atomicAdd(&g_deg[dst], w);
    atomicAdd(&g_cnt[dst], 1);
}

__global__ __launch_bounds__(1024)
void scan_kernel() {
    __shared__ int ssum[1024];
    const int C = (N_TOT + 1023) / 1024;
    int t = threadIdx.x;
    int beg = t * C, end = min(beg + C, N_TOT);
    int s = 0;
    for (int i = beg; i < end; ++i) s += g_cnt[i];
    ssum[t] = s;
    __syncthreads();
    for (int off = 1; off < 1024; off <<= 1) {
        int v = (t >= off) ? ssum[t - off] : 0;
        __syncthreads();
        ssum[t] += v;
        __syncthreads();
    }
    int run = ssum[t] - s;
    for (int i = beg; i < end; ++i) {
        g_rowptr[i] = run;
        g_cursor[i] = run;
        run += g_cnt[i];
    }
    if (t == 1023) g_rowptr[N_TOT] = ETOT;
}

__global__ void dinv_kernel() {
    int i = blockIdx.x * blockDim.x + threadIdx.x;
    if (i >= N_TOT) return;
    float d = g_deg[i];
    g_dinv[i] = (d > 0.0f) ? rsqrtf(d) : 0.0f;
}

__global__ void scatter_kernel(const int* __restrict__ aa_src, const int* __restrict__ aa_dst,
                               const float* __restrict__ len_aa,
                               const int* __restrict__ al_a, const int* __restrict__ al_l,
                               const float* __restrict__ len_al,
                               const float* __restrict__ w_e, const float* __restrict__ b_e) {
    int e = blockIdx.x * blockDim.x + threadIdx.x;
    if (e >= ETOT) return;
    int src, dst; float len;
    edge_decode(e, aa_src, aa_dst, len_aa, al_a, al_l, len_al, src, dst, len);
    float w = sigmoidf_(fmaf(len, w_e[0], b_e[0]));
    float nrm = g_dinv[src] * w * g_dinv[dst];
    int pos = atomicAdd(&g_cursor[dst], 1);
    g_epack[pos] = make_int2(src, __float_as_int(nrm));
}

// ---------------------------------------------------------------------------
__global__ __launch_bounds__(256)
void lin_kernel(const float* __restrict__ W, int in_sel, int use_bn) {
    __shared__ float Ws[64 * 65];
    __shared__ float xsh[64 * 65];
    const float* in = in_sel ? g_out1 : g_x;

    int tid = threadIdx.x;
    for (int idx = tid; idx < 64 * 64; idx += 256) {
        int k = idx >> 6, j = idx & 63;
        Ws[k * 65 + j] = W[idx];
    }
    int base = blockIdx.x * 64;
    for (int idx = tid; idx < 64 * 64; idx += 256) {
        int r = idx >> 6, k = idx & 63;
        int row = base + r;
        float v = (row < N_TOT) ? in[(size_t)row * 64 + k] : 0.0f;
        if (use_bn) v = fmaxf(fmaf(v, g_stats[128 + k], g_stats[192 + k]), 0.0f);
        xsh[r * 65 + k] = v;
    }
    __syncthreads();

    int j = tid & 63, rl = tid >> 6;
    for (int rr = rl; rr < 64; rr += 4) {
        float a = 0.0f;
#pragma unroll
        for (int k = 0; k < 64; ++k) a = fmaf(xsh[rr * 65 + k], Ws[k * 65 + j], a);
        int row = base + rr;
        if (row < N_TOT) g_h[(size_t)row * 64 + j] = a;
    }
}

// ---------------------------------------------------------------------------
__global__ __launch_bounds__(256)
void agg_csr_kernel(const float* __restrict__ bvec, float* __restrict__ dout, int map) {
    int node = blockIdx.x * 8 + (threadIdx.x >> 5);
    if (node >= N_TOT) return;
    int lane = threadIdx.x & 31;

    int beg = g_rowptr[node], end = g_rowptr[node + 1];

    float ax = 0.0f, ay = 0.0f;
    int e = beg;
    for (; e + 1 < end; e += 2) {
        int2 p0 = g_epack[e];
        int2 p1 = g_epack[e + 1];
        float2 v0 = *(const float2*)&g_h[(size_t)p0.x * 64 + 2 * lane];
        float2 v1 = *(const float2*)&g_h[(size_t)p1.x * 64 + 2 * lane];
        float n0 = __int_as_float(p0.y);
        float n1 = __int_as_float(p1.y);
        ax = fmaf(v0.x, n0, ax); ay = fmaf(v0.y, n0, ay);
        ax = fmaf(v1.x, n1, ax); ay = fmaf(v1.y, n1, ay);
    }
    if (e < end) {
        int2 p0 = g_epack[e];
        float2 v0 = *(const float2*)&g_h[(size_t)p0.x * 64 + 2 * lane];
        float n0 = __int_as_float(p0.y);
        ax = fmaf(v0.x, n0, ax); ay = fmaf(v0.y, n0, ay);
    }

    float di = g_dinv[node];
    float dd = di * di;
    float2 hv = *(const float2*)&g_h[(size_t)node * 64 + 2 * lane];
    float2 bv = *(const float2*)&bvec[2 * lane];
    float2 res;
    res.x = fmaf(hv.x, dd, ax) + bv.x;
    res.y = fmaf(hv.y, dd, ay) + bv.y;

    float* op;
    if (map) {
        size_t off = (node < A_TOT) ? ((size_t)(A_TOT + node) * 64)
                                    : ((size_t)(A_TOT + L_TOT + node) * 64);
        op = dout + off;
    } else {
        op = g_out1 + (size_t)node * 64;
    }
    *(float2*)(op + 2 * lane) = res;
}

// ---------------------------------------------------------------------------
__global__ __launch_bounds__(256)
void bn_stats_kernel() {
    __shared__ float sh[512];
    int tid = threadIdx.x;
    int j = tid & 63;
    float s = 0.0f, s2 = 0.0f;
    for (int row = blockIdx.x * 4 + (tid >> 6); row < N_TOT; row += gridDim.x * 4) {
        float v = g_out1[(size_t)row * 64 + j];
        s += v; s2 += v * v;
    }
    sh[tid] = s; sh[256 + tid] = s2;
    __syncthreads();
    if (tid < 64) {
        float t = sh[tid] + sh[tid + 64] + sh[tid + 128] + sh[tid + 192];
        atomicAdd(&g_stats[tid], t);
    } else if (tid < 128) {
        int jj = tid - 64;
        float t = sh[256 + jj] + sh[256 + jj + 64] + sh[256 + jj + 128] + sh[256 + jj + 192];
        atomicAdd(&g_stats[64 + jj], t);
    }
}

__global__ void bn_final_kernel(const float* __restrict__ gamma, const float* __restrict__ beta) {
    int j = threadIdx.x;
    if (j >= 64) return;
    float mean = g_stats[j] * (1.0f / N_TOT);
    float var  = g_stats[64 + j] * (1.0f / N_TOT) - mean * mean;
    float rs   = rsqrtf(var + BN_EPS);
    float sc   = rs * gamma[j];
    g_stats[128 + j] = sc;
    g_stats[192 + j] = beta[j] - mean * sc;
}

// ---------------------------------------------------------------------------
extern "C" void kernel_launch(void* const* d_in, const int* in_sizes, int n_in,
                              void* d_out, int out_size) {
    const float* agent_hist = (const float*)d_in[0];
    const float* lane_nodes = (const float*)d_in[1];
    const int*   eaa        = (const int*)d_in[2];
    const float* len_aa     = (const float*)d_in[3];
    const int*   eal        = (const int*)d_in[4];
    const float* len_al     = (const float*)d_in[5];
    const float* Wih_a      = (const float*)d_in[6];
    const float* Whh_a      = (const float*)d_in[7];
    const float* b_a        = (const float*)d_in[8];
    const float* Wih_l      = (const float*)d_in[9];
    const float* Whh_l      = (const float*)d_in[10];
    const float* b_l        = (const float*)d_in[11];
    const float* w_e        = (const float*)d_in[12];
    const float* b_e        = (const float*)d_in[13];
    const float* W1         = (const float*)d_in[14];
    const float* b1         = (const float*)d_in[15];
    const float* gamma1     = (const float*)d_in[16];
    const float* beta1      = (const float*)d_in[17];
    const float* W2         = (const float*)d_in[18];
    const float* b2         = (const float*)d_in[19];
    float* out = (float*)d_out;

    const int* aa_src = eaa;
    const int* aa_dst = eaa + E_AA;
    const int* al_a   = eal;
    const int* al_l   = eal + E_AL;

    const int smem_agent = SM_XS_OFF + 64 * 20 * 5 * 4;  // 194,560 B
    const int smem_lane  = SM_XS_OFF + 64 * 10 * 2 * 4;  // 174,080 B
    cudaFuncSetAttribute((const void*)lstm_mma_kernel<20, 5, false>,
                         cudaFuncAttributeMaxDynamicSharedMemorySize, smem_agent);
    cudaFuncSetAttribute((const void*)lstm_mma_kernel<10, 2, true>,
                         cudaFuncAttributeMaxDynamicSharedMemorySize, smem_lane);

    // CSR build first (ncu -s 5 lands on the agent LSTM)
    init_kernel<<<(N_TOT + 255) / 256, 256>>>();
    hist_kernel<<<(ETOT + 255) / 256, 256>>>(aa_src, aa_dst, len_aa, al_a, al_l, len_al, w_e, b_e);
    scan_kernel<<<1, 1024>>>();
    dinv_kernel<<<(N_TOT + 255) / 256, 256>>>();
    scatter_kernel<<<(ETOT + 255) / 256, 256>>>(aa_src, aa_dst, len_aa, al_a, al_l, len_al, w_e, b_e);

    // LSTMs (tensor cores via mma.sync)
    lstm_mma_kernel<20, 5, false><<<(A_TOT + 63) / 64, 256, smem_agent>>>(
        agent_hist, Wih_a, Whh_a, b_a, out, 0, A_TOT);
    lstm_mma_kernel<10, 2, true><<<(L_TOT + 63) / 64, 256, smem_lane>>>(
        lane_nodes, Wih_l, Whh_l, b_l, out + (size_t)2 * A_TOT * 64, A_TOT, L_TOT);

    // conv1
    lin_kernel<<<(N_TOT + 63) / 64, 256>>>(W1, 0, 0);
    agg_csr_kernel<<<(N_TOT + 7) / 8, 256>>>(b1, out, 0);

    // BN
    bn_stats_kernel<<<512, 256>>>();
    bn_final_kernel<<<1, 64>>>(gamma1, beta1);

    // conv2
    lin_kernel<<<(N_TOT + 63) / 64, 256>>>(W2, 1, 1);
    agg_csr_kernel<<<(N_TOT + 7) / 8, 256>>>(b2, out, 1);
}

// round 8
// speedup vs baseline: 2.0073x; 1.6034x over previous
#include <cuda_runtime.h>
#include <cuda_bf16.h>
#include <cstdint>

// ---------------------------------------------------------------------------
// Problem constants
// ---------------------------------------------------------------------------
#define A_TOT 20000
#define L_TOT 80000
#define N_TOT 100000
#define E_AA  400000
#define E_AL  800000
#define ETOT  (E_AA + 2 * E_AL)
#define HDIM  64
#define BN_EPS 1e-5f

typedef unsigned long long u64;

// ---------------------------------------------------------------------------
// Scratch (device globals)
// ---------------------------------------------------------------------------
__device__ float g_x[N_TOT * HDIM];
__device__ float g_h[N_TOT * HDIM];
__device__ float g_out1[N_TOT * HDIM];
__device__ float g_deg[N_TOT];
__device__ float g_dinv[N_TOT];
__device__ float g_stats[256];
__device__ int   g_cnt[N_TOT];
__device__ int   g_rowptr[N_TOT + 1];
__device__ int   g_cursor[N_TOT];
__device__ int2  g_epack[ETOT];

// ---------------------------------------------------------------------------
// math helpers
// ---------------------------------------------------------------------------
__device__ __forceinline__ float sigmoidf_(float x) {
    return 1.0f / (1.0f + __expf(-x));
}
__device__ __forceinline__ float tanh_fast(float x) {
    float y;
    asm("tanh.approx.f32 %0, %1;" : "=f"(y) : "f"(x));
    return y;
}
__device__ __forceinline__ float sig_fast(float x) {
    return fmaf(0.5f, tanh_fast(0.5f * x), 0.5f);
}
__device__ __forceinline__ void mma_bf16(float* d, const uint32_t* a,
                                         uint32_t b0, uint32_t b1) {
    asm volatile(
        "mma.sync.aligned.m16n8k16.row.col.f32.bf16.bf16.f32 "
        "{%0,%1,%2,%3}, {%4,%5,%6,%7}, {%8,%9}, {%0,%1,%2,%3};"
        : "+f"(d[0]), "+f"(d[1]), "+f"(d[2]), "+f"(d[3])
        : "r"(a[0]), "r"(a[1]), "r"(a[2]), "r"(a[3]), "r"(b0), "r"(b1));
}
__device__ __forceinline__ uint32_t pack_bf2(float a, float b) {
    __nv_bfloat16 ha = __float2bfloat16(a), hb = __float2bfloat16(b);
    return (uint32_t)__bfloat16_as_ushort(ha) |
           ((uint32_t)__bfloat16_as_ushort(hb) << 16);
}

// ---------------------------------------------------------------------------
// LSTM via mma.sync bf16 (3-term split precision), M=64 rows/block, 512 thr
//   A [64 rows][K=208] bf16: [h_hi(64) | h_lo(64) | h_hi(64) | x(16)]
//   B [256 cols][K=208] bf16: [W_hi | W_hi | W_lo | Xblk]
//   col n <- (gate g, unit u):  n = ((u>>3)<<5) + (g<<3) + (u&7)
//   16 warps as 2m x 8n, warp tile 32 rows x 32 cols
// ---------------------------------------------------------------------------
#define STRW 132            // row stride in words (528 B)
#define SM_B_OFF 33792      // A = 64*528
#define SM_XS_OFF 168960    // B = 256*528

template <int T, int D, bool MEAN>
__global__ __launch_bounds__(512, 1)
void lstm_mma_kernel(const float* __restrict__ xin,
                     const float* __restrict__ Wih,
                     const float* __restrict__ Whh,
                     const float* __restrict__ bias,
                     float* __restrict__ emb_out,
                     int xnode_off, int nrows)
{
    constexpr int TD = T * D;
    extern __shared__ char smem[];
    uint32_t* Aw = (uint32_t*)smem;
    uint32_t* Bw = (uint32_t*)(smem + SM_B_OFF);
    float*    xs = (float*)(smem + SM_XS_OFF);

    const int tid  = threadIdx.x;
    const int wid  = tid >> 5, lane = tid & 31;
    const int lrow = lane >> 2, q = lane & 3;
    const int wm = wid >> 3, wn = wid & 7;   // 2m x 8n warp grid
    const int base = blockIdx.x * 64;

    // ---- phase 1: zero A and B, load xs ----
    for (int i = tid; i < 64 * STRW; i += 512) Aw[i] = 0;
    for (int i = tid; i < 256 * STRW; i += 512) Bw[i] = 0;
    for (int idx = tid; idx < 64 * TD; idx += 512) {
        int r = idx / TD;
        xs[idx] = (base + r < nrows) ? xin[(size_t)base * TD + idx] : 0.0f;
    }
    __syncthreads();

    // ---- phase 2: fill B ----
    for (int idx = tid; idx < 256 * 64; idx += 512) {
        int j = idx >> 6, k = idx & 63;
        int g = j >> 6, u = j & 63;
        int n = ((u >> 3) << 5) + (g << 3) + (u & 7);
        float w = Whh[idx];
        __nv_bfloat16 hi = __float2bfloat16(w);
        __nv_bfloat16 lo = __float2bfloat16(w - __bfloat162float(hi));
        char* bp = smem + SM_B_OFF + n * 528;
        *(__nv_bfloat16*)(bp + 2 * k)       = hi;
        *(__nv_bfloat16*)(bp + 128 + 2 * k) = hi;
        *(__nv_bfloat16*)(bp + 256 + 2 * k) = lo;
    }
    if (tid < 256) {
        int j = tid;  // gate-row
        int g = j >> 6, u = j & 63;
        int n = ((u >> 3) << 5) + (g << 3) + (u & 7);
        char* bp = smem + SM_B_OFF + n * 528 + 384;
#pragma unroll
        for (int d = 0; d < D; ++d) {
            float w = Wih[j * D + d];
            __nv_bfloat16 hi = __float2bfloat16(w);
            __nv_bfloat16 lo = __float2bfloat16(w - __bfloat162float(hi));
            *(__nv_bfloat16*)(bp + 2 * d)           = hi;
            *(__nv_bfloat16*)(bp + 2 * (D + d))     = hi;
            *(__nv_bfloat16*)(bp + 2 * (2 * D + d)) = lo;
        }
        *(__nv_bfloat16*)(bp + 2 * (3 * D)) = __float2bfloat16(bias[j]);
    }
    // A: const 1 column + x(t=0)
    if (tid < 64) {
        *(__nv_bfloat16*)(smem + tid * 528 + 384 + 2 * (3 * D)) = __float2bfloat16(1.0f);
    }
    if (tid < 192) {
        int r = tid & 63, part = tid >> 6;
        const float* xr = xs + r * TD;
        char* ap = smem + r * 528 + 384;
#pragma unroll
        for (int d = 0; d < D; ++d) {
            float v = xr[d];
            __nv_bfloat16 hi = __float2bfloat16(v);
            if (part == 0)      *(__nv_bfloat16*)(ap + 2 * d) = hi;
            else if (part == 1) *(__nv_bfloat16*)(ap + 2 * (D + d)) =
                                    __float2bfloat16(v - __bfloat162float(hi));
            else                *(__nv_bfloat16*)(ap + 2 * (2 * D + d)) = hi;
        }
    }
    __syncthreads();

    float cst[8], outv[8];
#pragma unroll
    for (int i = 0; i < 8; ++i) { cst[i] = 0.0f; outv[i] = 0.0f; }

#pragma unroll 1
    for (int t = 0; t < T; ++t) {
        float acc[2][4][4];
#pragma unroll
        for (int mt = 0; mt < 2; ++mt)
#pragma unroll
            for (int nt = 0; nt < 4; ++nt)
#pragma unroll
                for (int i = 0; i < 4; ++i) acc[mt][nt][i] = 0.0f;

        const int ks0 = (t == 0) ? 12 : 0;
#pragma unroll 1
        for (int ks = ks0; ks < 13; ++ks) {
            uint32_t afr[2][4];
#pragma unroll
            for (int mt = 0; mt < 2; ++mt) {
                int w0 = (wm * 32 + mt * 16 + lrow) * STRW + ks * 8 + q;
                afr[mt][0] = Aw[w0];
                afr[mt][1] = Aw[w0 + 8 * STRW];
                afr[mt][2] = Aw[w0 + 4];
                afr[mt][3] = Aw[w0 + 8 * STRW + 4];
            }
#pragma unroll
            for (int nt = 0; nt < 4; ++nt) {
                int wb = (wn * 32 + nt * 8 + lrow) * STRW + ks * 8 + q;
                uint32_t b0 = Bw[wb], b1 = Bw[wb + 4];
                mma_bf16(acc[0][nt], afr[0], b0, b1);
                mma_bf16(acc[1][nt], afr[1], b0, b1);
            }
        }
        __syncthreads();   // all A reads done

        // epilogue: thread owns rows {wm*32+mt*16+lrow, +8}, units {wn*8+2q, +1}
#pragma unroll
        for (int mt = 0; mt < 2; ++mt)
#pragma unroll
            for (int half = 0; half < 2; ++half) {
                float hpair[2];
#pragma unroll
                for (int jp = 0; jp < 2; ++jp) {
                    int rg = half * 2 + jp;
                    float gi = acc[mt][0][rg];
                    float gf = acc[mt][1][rg];
                    float gg = acc[mt][2][rg];
                    float go = acc[mt][3][rg];
                    int ci = mt * 4 + half * 2 + jp;
                    float cn = fmaf(sig_fast(gf), cst[ci],
                                    sig_fast(gi) * tanh_fast(gg));
                    cst[ci] = cn;
                    float h = sig_fast(go) * tanh_fast(cn);
                    if (MEAN) outv[ci] += h; else outv[ci] = h;
                    hpair[jp] = h;
                }
                __nv_bfloat16 h0 = __float2bfloat16(hpair[0]);
                __nv_bfloat16 h1 = __float2bfloat16(hpair[1]);
                uint32_t hi2 = (uint32_t)__bfloat16_as_ushort(h0) |
                               ((uint32_t)__bfloat16_as_ushort(h1) << 16);
                uint32_t lo2 = pack_bf2(hpair[0] - __bfloat162float(h0),
                                        hpair[1] - __bfloat162float(h1));
                int row = wm * 32 + mt * 16 + half * 8 + lrow;
                int uw  = wn * 4 + q;
                Aw[row * STRW + uw]      = hi2;   // h_hi (k region 0)
                Aw[row * STRW + 32 + uw] = lo2;   // h_lo (k region 1)
                Aw[row * STRW + 64 + uw] = hi2;   // h_hi (k region 2)
            }

        // fill A_x for t+1
        if (t + 1 < T && tid < 192) {
            int r = tid & 63, part = tid >> 6;
            const float* xr = xs + r * TD + (t + 1) * D;
            char* ap = smem + r * 528 + 384;
#pragma unroll
            for (int d = 0; d < D; ++d) {
                float v = xr[d];
                __nv_bfloat16 hi = __float2bfloat16(v);
                if (part == 0)      *(__nv_bfloat16*)(ap + 2 * d) = hi;
                else if (part == 1) *(__nv_bfloat16*)(ap + 2 * (D + d)) =
                                        __float2bfloat16(v - __bfloat162float(hi));
                else                *(__nv_bfloat16*)(ap + 2 * (2 * D + d)) = hi;
            }
        }
        __syncthreads();
    }

    // outputs
    const float scale = MEAN ? (1.0f / T) : 1.0f;
#pragma unroll
    for (int mt = 0; mt < 2; ++mt)
#pragma unroll
        for (int half = 0; half < 2; ++half) {
            int grow = base + wm * 32 + mt * 16 + half * 8 + lrow;
            if (grow >= nrows) continue;
            int ci0 = mt * 4 + half * 2;
            int unit0 = wn * 8 + 2 * q;
            float2 v = make_float2(outv[ci0] * scale, outv[ci0 + 1] * scale);
            *(float2*)&emb_out[(size_t)grow * 64 + unit0] = v;
            *(float2*)&g_x[(size_t)(xnode_off + grow) * 64 + unit0] = v;
        }
}

// ---------------------------------------------------------------------------
// edge decode + CSR build
// ---------------------------------------------------------------------------
__device__ __forceinline__ void edge_decode(
    int e,
    const int* __restrict__ aa_src, const int* __restrict__ aa_dst,
    const float* __restrict__ len_aa,
    const int* __restrict__ al_a, const int* __restrict__ al_l,
    const float* __restrict__ len_al,
    int& src, int& dst, float& len)
{
    if (e < E_AA) {
        src = aa_src[e]; dst = aa_dst[e]; len = len_aa[e];
    } else if (e < E_AA + E_AL) {
        int i = e - E_AA;
        src = al_a[i]; dst = A_TOT + al_l[i]; len = len_al[i];
    } else {
        int i = e - E_AA - E_AL;
        src = A_TOT + al_l[i]; dst = al_a[i]; len = len_al[i];
    }
}

__global__ void init_kernel() {
    int i = blockIdx.x * blockDim.x + threadIdx.x;
    if (i < N_TOT) { g_deg[i] = 1.0f; g_cnt[i] = 0; }
    if (i < 256) g_stats[i] = 0.0f;
}

__global__ void hist_kernel(const int* __restrict__ aa_src, const int* __restrict__ aa_dst,
                            const float* __restrict__ len_aa,
                            const int* __restrict__ al_a, const int* __restrict__ al_l,
                            const float* __restrict__ len_al,
                            const float* __restrict__ w_e, const float* __restrict__ b_e) {
    int e = blockIdx.x * blockDim.x + threadIdx.x;
    if (e >= ETOT) return;
    int src, dst; float len;
    edge_decode(e, aa_src, aa_dst, len_aa, al_a, al_l, len_al, src, dst, len);
    float w = sigmoidf_(fmaf(len, w_e[0], b_e[0]));
    atomicAdd(&g_deg[dst], w);
    atomicAdd(&g_cnt[dst], 1);
}

__global__ __launch_bounds__(1024)
void scan_kernel() {
    __shared__ int ssum[1024];
    const int C = (N_TOT + 1023) / 1024;
    int t = threadIdx.x;
    int beg = t * C, end = min(beg + C, N_TOT);
    int s = 0;
    for (int i = beg; i < end; ++i) s += g_cnt[i];
    ssum[t] = s;
    __syncthreads();
    for (int off = 1; off < 1024; off <<= 1) {
        int v = (t >= off) ? ssum[t - off] : 0;
        __syncthreads();
        ssum[t] += v;
        __syncthreads();
    }
    int run = ssum[t] - s;
    for (int i = beg; i < end; ++i) {
        g_rowptr[i] = run;
        g_cursor[i] = run;
        run += g_cnt[i];
    }
    if (t == 1023) g_rowptr[N_TOT] = ETOT;
}

__global__ void dinv_kernel() {
    int i = blockIdx.x * blockDim.x + threadIdx.x;
    if (i >= N_TOT) return;
    float d = g_deg[i];
    g_dinv[i] = (d > 0.0f) ? rsqrtf(d) : 0.0f;
}

__global__ void scatter_kernel(const int* __restrict__ aa_src, const int* __restrict__ aa_dst,
                               const float* __restrict__ len_aa,
                               const int* __restrict__ al_a, const int* __restrict__ al_l,
                               const float* __restrict__ len_al,
                               const float* __restrict__ w_e, const float* __restrict__ b_e) {
    int e = blockIdx.x * blockDim.x + threadIdx.x;
    if (e >= ETOT) return;
    int src, dst; float len;
    edge_decode(e, aa_src, aa_dst, len_aa, al_a, al_l, len_al, src, dst, len);
    float w = sigmoidf_(fmaf(len, w_e[0], b_e[0]));
    float nrm = g_dinv[src] * w * g_dinv[dst];
    int pos = atomicAdd(&g_cursor[dst], 1);
    g_epack[pos] = make_int2(src, __float_as_int(nrm));
}

// ---------------------------------------------------------------------------
__global__ __launch_bounds__(256)
void lin_kernel(const float* __restrict__ W, int in_sel, int use_bn) {
    __shared__ float Ws[64 * 65];
    __shared__ float xsh[64 * 65];
    const float* in = in_sel ? g_out1 : g_x;

    int tid = threadIdx.x;
    for (int idx = tid; idx < 64 * 64; idx += 256) {
        int k = idx >> 6, j = idx & 63;
        Ws[k * 65 + j] = W[idx];
    }
    int base = blockIdx.x * 64;
    for (int idx = tid; idx < 64 * 64; idx += 256) {
        int r = idx >> 6, k = idx & 63;
        int row = base + r;
        float v = (row < N_TOT) ? in[(size_t)row * 64 + k] : 0.0f;
        if (use_bn) v = fmaxf(fmaf(v, g_stats[128 + k], g_stats[192 + k]), 0.0f);
        xsh[r * 65 + k] = v;
    }
    __syncthreads();

    int j = tid & 63, rl = tid >> 6;
    for (int rr = rl; rr < 64; rr += 4) {
        float a = 0.0f;
#pragma unroll
        for (int k = 0; k < 64; ++k) a = fmaf(xsh[rr * 65 + k], Ws[k * 65 + j], a);
        int row = base + rr;
        if (row < N_TOT) g_h[(size_t)row * 64 + j] = a;
    }
}

// ---------------------------------------------------------------------------
__global__ __launch_bounds__(256)
void agg_csr_kernel(const float* __restrict__ bvec, float* __restrict__ dout, int map) {
    int node = blockIdx.x * 8 + (threadIdx.x >> 5);
    if (node >= N_TOT) return;
    int lane = threadIdx.x & 31;

    int beg = g_rowptr[node], end = g_rowptr[node + 1];

    float ax = 0.0f, ay = 0.0f;
    int e = beg;
    for (; e + 1 < end; e += 2) {
        int2 p0 = g_epack[e];
        int2 p1 = g_epack[e + 1];
        float2 v0 = *(const float2*)&g_h[(size_t)p0.x * 64 + 2 * lane];
        float2 v1 = *(const float2*)&g_h[(size_t)p1.x * 64 + 2 * lane];
        float n0 = __int_as_float(p0.y);
        float n1 = __int_as_float(p1.y);
        ax = fmaf(v0.x, n0, ax); ay = fmaf(v0.y, n0, ay);
        ax = fmaf(v1.x, n1, ax); ay = fmaf(v1.y, n1, ay);
    }
    if (e < end) {
        int2 p0 = g_epack[e];
        float2 v0 = *(const float2*)&g_h[(size_t)p0.x * 64 + 2 * lane];
        float n0 = __int_as_float(p0.y);
        ax = fmaf(v0.x, n0, ax); ay = fmaf(v0.y, n0, ay);
    }

    float di = g_dinv[node];
    float dd = di * di;
    float2 hv = *(const float2*)&g_h[(size_t)node * 64 + 2 * lane];
    float2 bv = *(const float2*)&bvec[2 * lane];
    float2 res;
    res.x = fmaf(hv.x, dd, ax) + bv.x;
    res.y = fmaf(hv.y, dd, ay) + bv.y;

    float* op;
    if (map) {
        size_t off = (node < A_TOT) ? ((size_t)(A_TOT + node) * 64)
                                    : ((size_t)(A_TOT + L_TOT + node) * 64);
        op = dout + off;
    } else {
        op = g_out1 + (size_t)node * 64;
    }
    *(float2*)(op + 2 * lane) = res;
}

// ---------------------------------------------------------------------------
__global__ __launch_bounds__(256)
void bn_stats_kernel() {
    __shared__ float sh[512];
    int tid = threadIdx.x;
    int j = tid & 63;
    float s = 0.0f, s2 = 0.0f;
    for (int row = blockIdx.x * 4 + (tid >> 6); row < N_TOT; row += gridDim.x * 4) {
        float v = g_out1[(size_t)row * 64 + j];
        s += v; s2 += v * v;
    }
    sh[tid] = s; sh[256 + tid] = s2;
    __syncthreads();
    if (tid < 64) {
        float t = sh[tid] + sh[tid + 64] + sh[tid + 128] + sh[tid + 192];
        atomicAdd(&g_stats[tid], t);
    } else if (tid < 128) {
        int jj = tid - 64;
        float t = sh[256 + jj] + sh[256 + jj + 64] + sh[256 + jj + 128] + sh[256 + jj + 192];
        atomicAdd(&g_stats[64 + jj], t);
    }
}

__global__ void bn_final_kernel(const float* __restrict__ gamma, const float* __restrict__ beta) {
    int j = threadIdx.x;
    if (j >= 64) return;
    float mean = g_stats[j] * (1.0f / N_TOT);
    float var  = g_stats[64 + j] * (1.0f / N_TOT) - mean * mean;
    float rs   = rsqrtf(var + BN_EPS);
    float sc   = rs * gamma[j];
    g_stats[128 + j] = sc;
    g_stats[192 + j] = beta[j] - mean * sc;
}

// ---------------------------------------------------------------------------
extern "C" void kernel_launch(void* const* d_in, const int* in_sizes, int n_in,
                              void* d_out, int out_size) {
    const float* agent_hist = (const float*)d_in[0];
    const float* lane_nodes = (const float*)d_in[1];
    const int*   eaa        = (const int*)d_in[2];
    const float* len_aa     = (const float*)d_in[3];
    const int*   eal        = (const int*)d_in[4];
    const float* len_al     = (const float*)d_in[5];
    const float* Wih_a      = (const float*)d_in[6];
    const float* Whh_a      = (const float*)d_in[7];
    const float* b_a        = (const float*)d_in[8];
    const float* Wih_l      = (const float*)d_in[9];
    const float* Whh_l      = (const float*)d_in[10];
    const float* b_l        = (const float*)d_in[11];
    const float* w_e        = (const float*)d_in[12];
    const float* b_e        = (const float*)d_in[13];
    const float* W1         = (const float*)d_in[14];
    const float* b1         = (const float*)d_in[15];
    const float* gamma1     = (const float*)d_in[16];
    const float* beta1      = (const float*)d_in[17];
    const float* W2         = (const float*)d_in[18];
    const float* b2         = (const float*)d_in[19];
    float* out = (float*)d_out;

    const int* aa_src = eaa;
    const int* aa_dst = eaa + E_AA;
    const int* al_a   = eal;
    const int* al_l   = eal + E_AL;

    const int smem_agent = SM_XS_OFF + 64 * 20 * 5 * 4;  // 194,560 B
    const int smem_lane  = SM_XS_OFF + 64 * 10 * 2 * 4;  // 174,080 B
    cudaFuncSetAttribute((const void*)lstm_mma_kernel<20, 5, false>,
                         cudaFuncAttributeMaxDynamicSharedMemorySize, smem_agent);
    cudaFuncSetAttribute((const void*)lstm_mma_kernel<10, 2, true>,
                         cudaFuncAttributeMaxDynamicSharedMemorySize, smem_lane);

    // launch order arranged so the agent LSTM is launch index 3 (ncu target)
    init_kernel<<<(N_TOT + 255) / 256, 256>>>();
    hist_kernel<<<(ETOT + 255) / 256, 256>>>(aa_src, aa_dst, len_aa, al_a, al_l, len_al, w_e, b_e);
    scan_kernel<<<1, 1024>>>();

    lstm_mma_kernel<20, 5, false><<<(A_TOT + 63) / 64, 512, smem_agent>>>(
        agent_hist, Wih_a, Whh_a, b_a, out, 0, A_TOT);
    lstm_mma_kernel<10, 2, true><<<(L_TOT + 63) / 64, 512, smem_lane>>>(
        lane_nodes, Wih_l, Whh_l, b_l, out + (size_t)2 * A_TOT * 64, A_TOT, L_TOT);

    dinv_kernel<<<(N_TOT + 255) / 256, 256>>>();
    scatter_kernel<<<(ETOT + 255) / 256, 256>>>(aa_src, aa_dst, len_aa, al_a, al_l, len_al, w_e, b_e);

    // conv1
    lin_kernel<<<(N_TOT + 63) / 64, 256>>>(W1, 0, 0);
    agg_csr_kernel<<<(N_TOT + 7) / 8, 256>>>(b1, out, 0);

    // BN
    bn_stats_kernel<<<512, 256>>>();
    bn_final_kernel<<<1, 64>>>(gamma1, beta1);

    // conv2
    lin_kernel<<<(N_TOT + 63) / 64, 256>>>(W2, 1, 1);
    agg_csr_kernel<<<(N_TOT + 7) / 8, 256>>>(b2, out, 1);
}

// round 9
// speedup vs baseline: 2.2882x; 1.1400x over previous
#include <cuda_runtime.h>
#include <cuda_bf16.h>
#include <cstdint>

// ---------------------------------------------------------------------------
// Problem constants
// ---------------------------------------------------------------------------
#define A_TOT 20000
#define L_TOT 80000
#define N_TOT 100000
#define E_AA  400000
#define E_AL  800000
#define ETOT  (E_AA + 2 * E_AL)
#define HDIM  64
#define BN_EPS 1e-5f

typedef unsigned long long u64;

// ---------------------------------------------------------------------------
// Scratch (device globals)
// ---------------------------------------------------------------------------
__device__ float g_x[N_TOT * HDIM];
__device__ float g_h[N_TOT * HDIM];
__device__ float g_out1[N_TOT * HDIM];
__device__ float g_deg[N_TOT];
__device__ float g_dinv[N_TOT];
__device__ float g_stats[256];
__device__ int   g_cnt[N_TOT];
__device__ int   g_rowptr[N_TOT + 1];
__device__ int   g_cursor[N_TOT];
__device__ int2  g_epack[ETOT];

// ---------------------------------------------------------------------------
// math helpers
// ---------------------------------------------------------------------------
__device__ __forceinline__ float sigmoidf_(float x) {
    return 1.0f / (1.0f + __expf(-x));
}
__device__ __forceinline__ float tanh_fast(float x) {
    float y;
    asm("tanh.approx.f32 %0, %1;" : "=f"(y) : "f"(x));
    return y;
}
__device__ __forceinline__ float sig_fast(float x) {
    return fmaf(0.5f, tanh_fast(0.5f * x), 0.5f);
}
__device__ __forceinline__ void mma_bf16(float* d, const uint32_t* a,
                                         uint32_t b0, uint32_t b1) {
    asm volatile(
        "mma.sync.aligned.m16n8k16.row.col.f32.bf16.bf16.f32 "
        "{%0,%1,%2,%3}, {%4,%5,%6,%7}, {%8,%9}, {%0,%1,%2,%3};"
        : "+f"(d[0]), "+f"(d[1]), "+f"(d[2]), "+f"(d[3])
        : "r"(a[0]), "r"(a[1]), "r"(a[2]), "r"(a[3]), "r"(b0), "r"(b1));
}
#define LDSM4(r, addr)                                                        \
    asm volatile("ldmatrix.sync.aligned.m8n8.x4.shared.b16 {%0,%1,%2,%3}, [%4];" \
        : "=r"((r)[0]), "=r"((r)[1]), "=r"((r)[2]), "=r"((r)[3]) : "r"(addr))

__device__ __forceinline__ uint32_t smem_u32(const void* p) {
    uint32_t a;
    asm("{ .reg .u64 t; cvta.to.shared.u64 t, %1; cvt.u32.u64 %0, t; }"
        : "=r"(a) : "l"(p));
    return a;
}
__device__ __forceinline__ uint32_t pack_bf2(float a, float b) {
    __nv_bfloat16 ha = __float2bfloat16(a), hb = __float2bfloat16(b);
    return (uint32_t)__bfloat16_as_ushort(ha) |
           ((uint32_t)__bfloat16_as_ushort(hb) << 16);
}
__device__ __forceinline__ float bf_lo(uint32_t v) {
    return __bfloat162float(__ushort_as_bfloat16((unsigned short)(v & 0xFFFF)));
}
__device__ __forceinline__ float bf_hi(uint32_t v) {
    return __bfloat162float(__ushort_as_bfloat16((unsigned short)(v >> 16)));
}

// ---------------------------------------------------------------------------
// LSTM via mma.sync bf16, deduped B, ldmatrix operand loads.
//   A [64 rows][K=144] bf16: [h_hi(64) | h_lo(64) | x(16)]   stride 304 B
//   B [256 cols][K=144] bf16: [W_hi(64) | W_lo(64) | Xblk(16)] stride 304 B
//   passes (aK,bK): (0,0) (64,0) (0,64) + x-pass (128,128)
//   col n <- (gate g, unit u):  n = ((u>>3)<<5) + (g<<3) + (u&7)
//   512 thr, 16 warps 2m x 8n, warp tile 32 rows x 32 cols; 2 blocks/SM
// ---------------------------------------------------------------------------
#define BSTR 304
#define SM_B_OFF (64 * BSTR)
#define LSTM_SMEM (64 * BSTR + 256 * BSTR)   // 97,280 B

template <int T, int D, bool MEAN>
__global__ __launch_bounds__(512, 2)
void lstm_mma_kernel(const float* __restrict__ xin,
                     const float* __restrict__ Wih,
                     const float* __restrict__ Whh,
                     const float* __restrict__ bias,
                     float* __restrict__ emb_out,
                     int xnode_off, int nrows)
{
    constexpr int TD = T * D;
    extern __shared__ char smem[];
    uint32_t* Aw = (uint32_t*)smem;
    const uint32_t sb = smem_u32(smem);

    const int tid  = threadIdx.x;
    const int wid  = tid >> 5, lane = tid & 31;
    const int lrow = lane >> 2, q = lane & 3;
    const int wm = wid >> 3, wn = wid & 7;   // 2m x 8n warp grid
    const int base = blockIdx.x * 64;

    // ---- zero A + B ----
    for (int i = tid; i < (64 + 256) * (BSTR / 4); i += 512) Aw[i] = 0;
    __syncthreads();

    // ---- fill B: W_hi (k0-63), W_lo (k64-127) ----
    for (int idx = tid; idx < 256 * 64; idx += 512) {
        int j = idx >> 6, k = idx & 63;
        int g = j >> 6, u = j & 63;
        int n = ((u >> 3) << 5) + (g << 3) + (u & 7);
        float w = Whh[idx];
        __nv_bfloat16 hi = __float2bfloat16(w);
        __nv_bfloat16 lo = __float2bfloat16(w - __bfloat162float(hi));
        char* bp = smem + SM_B_OFF + n * BSTR;
        *(__nv_bfloat16*)(bp + 2 * k)       = hi;
        *(__nv_bfloat16*)(bp + 128 + 2 * k) = lo;
    }
    // X block (k128-143): [Wih_hi | Wih_hi | Wih_lo | bias]
    if (tid < 256) {
        int j = tid;
        int g = j >> 6, u = j & 63;
        int n = ((u >> 3) << 5) + (g << 3) + (u & 7);
        char* bp = smem + SM_B_OFF + n * BSTR + 256;
#pragma unroll
        for (int d = 0; d < D; ++d) {
            float w = Wih[j * D + d];
            __nv_bfloat16 hi = __float2bfloat16(w);
            __nv_bfloat16 lo = __float2bfloat16(w - __bfloat162float(hi));
            *(__nv_bfloat16*)(bp + 2 * d)           = hi;
            *(__nv_bfloat16*)(bp + 2 * (D + d))     = hi;
            *(__nv_bfloat16*)(bp + 2 * (2 * D + d)) = lo;
        }
        *(__nv_bfloat16*)(bp + 2 * (3 * D)) = __float2bfloat16(bias[j]);
    }
    // A x block for t=0: [x_hi | x_lo | x_hi | 1]
    if (tid < 64) {
        *(__nv_bfloat16*)(smem + tid * BSTR + 256 + 2 * (3 * D)) = __float2bfloat16(1.0f);
    }
    if (tid < 192) {
        int r = tid & 63, part = tid >> 6;
        char* ap = smem + r * BSTR + 256;
        bool ok = (base + r < nrows);
        const float* xr = xin + (size_t)(base + r) * TD;
#pragma unroll
        for (int d = 0; d < D; ++d) {
            float v = ok ? xr[d] : 0.0f;
            __nv_bfloat16 hi = __float2bfloat16(v);
            if (part == 0)      *(__nv_bfloat16*)(ap + 2 * d) = hi;
            else if (part == 1) *(__nv_bfloat16*)(ap + 2 * (D + d)) =
                                    __float2bfloat16(v - __bfloat162float(hi));
            else                *(__nv_bfloat16*)(ap + 2 * (2 * D + d)) = hi;
        }
    }
    __syncthreads();

    // ldmatrix lane base addresses
    const uint32_t aAddr0 = sb + (uint32_t)(wm * 32 + (lane & 15)) * BSTR
                          + (uint32_t)((lane >> 4) * 8) * 2;
    const uint32_t bAddr0 = sb + SM_B_OFF
                          + (uint32_t)(wn * 32 + (lane >> 4) * 8 + (lane & 7)) * BSTR
                          + (uint32_t)(((lane >> 3) & 1)) * 16;

    float cst[8], outv[8];
#pragma unroll
    for (int i = 0; i < 8; ++i) { cst[i] = 0.0f; outv[i] = 0.0f; }

#pragma unroll 1
    for (int t = 0; t < T; ++t) {
        float acc[2][4][4];
#pragma unroll
        for (int mt = 0; mt < 2; ++mt)
#pragma unroll
            for (int nt = 0; nt < 4; ++nt)
#pragma unroll
                for (int i = 0; i < 4; ++i) acc[mt][nt][i] = 0.0f;

        if (t > 0) {
#pragma unroll 1
            for (int p = 0; p < 3; ++p) {
                const uint32_t aK2 = (p == 1) ? 128u : 0u;   // bytes: h_lo at 128
                const uint32_t bK2 = (p == 2) ? 128u : 0u;   // bytes: W_lo at 128
#pragma unroll
                for (int ks = 0; ks < 4; ++ks) {
                    uint32_t ka = aK2 + ks * 32, kb = bK2 + ks * 32;
                    uint32_t a0[4], a1[4], q0[4], q1[4];
                    LDSM4(a0, aAddr0 + ka);
                    LDSM4(a1, aAddr0 + 16 * BSTR + ka);
                    LDSM4(q0, bAddr0 + kb);
                    LDSM4(q1, bAddr0 + 16 * BSTR + kb);
                    mma_bf16(acc[0][0], a0, q0[0], q0[1]);
                    mma_bf16(acc[0][1], a0, q0[2], q0[3]);
                    mma_bf16(acc[0][2], a0, q1[0], q1[1]);
                    mma_bf16(acc[0][3], a0, q1[2], q1[3]);
                    mma_bf16(acc[1][0], a1, q0[0], q0[1]);
                    mma_bf16(acc[1][1], a1, q0[2], q0[3]);
                    mma_bf16(acc[1][2], a1, q1[0], q1[1]);
                    mma_bf16(acc[1][3], a1, q1[2], q1[3]);
                }
            }
        }
        // x pass (k bytes 256)
        {
            uint32_t a0[4], a1[4], q0[4], q1[4];
            LDSM4(a0, aAddr0 + 256);
            LDSM4(a1, aAddr0 + 16 * BSTR + 256);
            LDSM4(q0, bAddr0 + 256);
            LDSM4(q1, bAddr0 + 16 * BSTR + 256);
            mma_bf16(acc[0][0], a0, q0[0], q0[1]);
            mma_bf16(acc[0][1], a0, q0[2], q0[3]);
            mma_bf16(acc[0][2], a0, q1[0], q1[1]);
            mma_bf16(acc[0][3], a0, q1[2], q1[3]);
            mma_bf16(acc[1][0], a1, q0[0], q0[1]);
            mma_bf16(acc[1][1], a1, q0[2], q0[3]);
            mma_bf16(acc[1][2], a1, q1[0], q1[1]);
            mma_bf16(acc[1][3], a1, q1[2], q1[3]);
        }
        __syncthreads();   // all A reads done

        // epilogue
#pragma unroll
        for (int mt = 0; mt < 2; ++mt)
#pragma unroll
            for (int half = 0; half < 2; ++half) {
                float hpair[2];
#pragma unroll
                for (int jp = 0; jp < 2; ++jp) {
                    int rg = half * 2 + jp;
                    float gi = acc[mt][0][rg];
                    float gf = acc[mt][1][rg];
                    float gg = acc[mt][2][rg];
                    float go = acc[mt][3][rg];
                    int ci = mt * 4 + half * 2 + jp;
                    float cn = fmaf(sig_fast(gf), cst[ci],
                                    sig_fast(gi) * tanh_fast(gg));
                    cst[ci] = cn;
                    float h = sig_fast(go) * tanh_fast(cn);
                    if (MEAN) outv[ci] += h;
                    hpair[jp] = h;
                }
                __nv_bfloat16 h0 = __float2bfloat16(hpair[0]);
                __nv_bfloat16 h1 = __float2bfloat16(hpair[1]);
                uint32_t hi2 = (uint32_t)__bfloat16_as_ushort(h0) |
                               ((uint32_t)__bfloat16_as_ushort(h1) << 16);
                uint32_t lo2 = pack_bf2(hpair[0] - __bfloat162float(h0),
                                        hpair[1] - __bfloat162float(h1));
                int row = wm * 32 + mt * 16 + half * 8 + lrow;
                int uw  = wn * 4 + q;
                Aw[row * (BSTR / 4) + uw]      = hi2;   // h_hi
                Aw[row * (BSTR / 4) + 32 + uw] = lo2;   // h_lo
            }

        // fill A_x for t+1 (direct from gmem)
        if (t + 1 < T && tid < 192) {
            int r = tid & 63, part = tid >> 6;
            char* ap = smem + r * BSTR + 256;
            bool ok = (base + r < nrows);
            const float* xr = xin + (size_t)(base + r) * TD + (t + 1) * D;
#pragma unroll
            for (int d = 0; d < D; ++d) {
                float v = ok ? xr[d] : 0.0f;
                __nv_bfloat16 hi = __float2bfloat16(v);
                if (part == 0)      *(__nv_bfloat16*)(ap + 2 * d) = hi;
                else if (part == 1) *(__nv_bfloat16*)(ap + 2 * (D + d)) =
                                        __float2bfloat16(v - __bfloat162float(hi));
                else                *(__nv_bfloat16*)(ap + 2 * (2 * D + d)) = hi;
            }
        }
        __syncthreads();
    }

    // outputs
    const float scale = MEAN ? (1.0f / T) : 1.0f;
#pragma unroll
    for (int mt = 0; mt < 2; ++mt)
#pragma unroll
        for (int half = 0; half < 2; ++half) {
            int row = wm * 32 + mt * 16 + half * 8 + lrow;
            int grow = base + row;
            if (grow >= nrows) continue;
            int unit0 = wn * 8 + 2 * q;
            float2 v;
            if (MEAN) {
                int ci0 = mt * 4 + half * 2;
                v = make_float2(outv[ci0] * scale, outv[ci0 + 1] * scale);
            } else {
                uint32_t hi2 = Aw[row * (BSTR / 4) + wn * 4 + q];
                uint32_t lo2 = Aw[row * (BSTR / 4) + 32 + wn * 4 + q];
                v = make_float2(bf_lo(hi2) + bf_lo(lo2), bf_hi(hi2) + bf_hi(lo2));
            }
            *(float2*)&emb_out[(size_t)grow * 64 + unit0] = v;
            *(float2*)&g_x[(size_t)(xnode_off + grow) * 64 + unit0] = v;
        }
}

// ---------------------------------------------------------------------------
// edge decode + CSR build
// ---------------------------------------------------------------------------
__device__ __forceinline__ void edge_decode(
    int e,
    const int* __restrict__ aa_src, const int* __restrict__ aa_dst,
    const float* __restrict__ len_aa,
    const int* __restrict__ al_a, const int* __restrict__ al_l,
    const float* __restrict__ len_al,
    int& src, int& dst, float& len)
{
    if (e < E_AA) {
        src = aa_src[e]; dst = aa_dst[e]; len = len_aa[e];
    } else if (e < E_AA + E_AL) {
        int i = e - E_AA;
        src = al_a[i]; dst = A_TOT + al_l[i]; len = len_al[i];
    } else {
        int i = e - E_AA - E_AL;
        src = A_TOT + al_l[i]; dst = al_a[i]; len = len_al[i];
    }
}

__global__ void init_kernel() {
    int i = blockIdx.x * blockDim.x + threadIdx.x;
    if (i < N_TOT) { g_deg[i] = 1.0f; g_cnt[i] = 0; }
    if (i < 256) g_stats[i] = 0.0f;
}

__global__ void hist_kernel(const int* __restrict__ aa_src, const int* __restrict__ aa_dst,
                            const float* __restrict__ len_aa,
                            const int* __restrict__ al_a, const int* __restrict__ al_l,
                            const float* __restrict__ len_al,
                            const float* __restrict__ w_e, const float* __restrict__ b_e) {
    int e = blockIdx.x * blockDim.x + threadIdx.x;
    if (e >= ETOT) return;
    int src, dst; float len;
    edge_decode(e, aa_src, aa_dst, len_aa, al_a, al_l, len_al, src, dst, len);
    float w = sigmoidf_(fmaf(len, w_e[0], b_e[0]));
    atomicAdd(&g_deg[dst], w);
    atomicAdd(&g_cnt[dst], 1);
}

__global__ __launch_bounds__(1024)
void scan_kernel() {
    __shared__ int ssum[1024];
    const int C = (N_TOT + 1023) / 1024;
    int t = threadIdx.x;
    int beg = t * C, end = min(beg + C, N_TOT);
    int s = 0;
    for (int i = beg; i < end; ++i) s += g_cnt[i];
    ssum[t] = s;
    __syncthreads();
    for (int off = 1; off < 1024; off <<= 1) {
        int v = (t >= off) ? ssum[t - off] : 0;
        __syncthreads();
        ssum[t] += v;
        __syncthreads();
    }
    int run = ssum[t] - s;
    for (int i = beg; i < end; ++i) {
        g_rowptr[i] = run;
        g_cursor[i] = run;
        run += g_cnt[i];
    }
    if (t == 1023) g_rowptr[N_TOT] = ETOT;
}

__global__ void dinv_kernel() {
    int i = blockIdx.x * blockDim.x + threadIdx.x;
    if (i >= N_TOT) return;
    float d = g_deg[i];
    g_dinv[i] = (d > 0.0f) ? rsqrtf(d) : 0.0f;
}

__global__ void scatter_kernel(const int* __restrict__ aa_src, const int* __restrict__ aa_dst,
                               const float* __restrict__ len_aa,
                               const int* __restrict__ al_a, const int* __restrict__ al_l,
                               const float* __restrict__ len_al,
                               const float* __restrict__ w_e, const float* __restrict__ b_e) {
    int e = blockIdx.x * blockDim.x + threadIdx.x;
    if (e >= ETOT) return;
    int src, dst; float len;
    edge_decode(e, aa_src, aa_dst, len_aa, al_a, al_l, len_al, src, dst, len);
    float w = sigmoidf_(fmaf(len, w_e[0], b_e[0]));
    float nrm = g_dinv[src] * w * g_dinv[dst];
    int pos = atomicAdd(&g_cursor[dst], 1);
    g_epack[pos] = make_int2(src, __float_as_int(nrm));
}

// ---------------------------------------------------------------------------
__global__ __launch_bounds__(256)
void lin_kernel(const float* __restrict__ W, int in_sel, int use_bn) {
    __shared__ float Ws[64 * 65];
    __shared__ float xsh[64 * 65];
    const float* in = in_sel ? g_out1 : g_x;

    int tid = threadIdx.x;
    for (int idx = tid; idx < 64 * 64; idx += 256) {
        int k = idx >> 6, j = idx & 63;
        Ws[k * 65 + j] = W[idx];
    }
    int base = blockIdx.x * 64;
    for (int idx = tid; idx < 64 * 64; idx += 256) {
        int r = idx >> 6, k = idx & 63;
        int row = base + r;
        float v = (row < N_TOT) ? in[(size_t)row * 64 + k] : 0.0f;
        if (use_bn) v = fmaxf(fmaf(v, g_stats[128 + k], g_stats[192 + k]), 0.0f);
        xsh[r * 65 + k] = v;
    }
    __syncthreads();

    int j = tid & 63, rl = tid >> 6;
    for (int rr = rl; rr < 64; rr += 4) {
        float a = 0.0f;
#pragma unroll
        for (int k = 0; k < 64; ++k) a = fmaf(xsh[rr * 65 + k], Ws[k * 65 + j], a);
        int row = base + rr;
        if (row < N_TOT) g_h[(size_t)row * 64 + j] = a;
    }
}

// ---------------------------------------------------------------------------
__global__ __launch_bounds__(256)
void agg_csr_kernel(const float* __restrict__ bvec, float* __restrict__ dout, int map) {
    int node = blockIdx.x * 8 + (threadIdx.x >> 5);
    if (node >= N_TOT) return;
    int lane = threadIdx.x & 31;

    int beg = g_rowptr[node], end = g_rowptr[node + 1];

    float ax = 0.0f, ay = 0.0f;
    int e = beg;
    for (; e + 1 < end; e += 2) {
        int2 p0 = g_epack[e];
        int2 p1 = g_epack[e + 1];
        float2 v0 = *(const float2*)&g_h[(size_t)p0.x * 64 + 2 * lane];
        float2 v1 = *(const float2*)&g_h[(size_t)p1.x * 64 + 2 * lane];
        float n0 = __int_as_float(p0.y);
        float n1 = __int_as_float(p1.y);
        ax = fmaf(v0.x, n0, ax); ay = fmaf(v0.y, n0, ay);
        ax = fmaf(v1.x, n1, ax); ay = fmaf(v1.y, n1, ay);
    }
    if (e < end) {
        int2 p0 = g_epack[e];
        float2 v0 = *(const float2*)&g_h[(size_t)p0.x * 64 + 2 * lane];
        float n0 = __int_as_float(p0.y);
        ax = fmaf(v0.x, n0, ax); ay = fmaf(v0.y, n0, ay);
    }

    float di = g_dinv[node];
    float dd = di * di;
    float2 hv = *(const float2*)&g_h[(size_t)node * 64 + 2 * lane];
    float2 bv = *(const float2*)&bvec[2 * lane];
    float2 res;
    res.x = fmaf(hv.x, dd, ax) + bv.x;
    res.y = fmaf(hv.y, dd, ay) + bv.y;

    float* op;
    if (map) {
        size_t off = (node < A_TOT) ? ((size_t)(A_TOT + node) * 64)
                                    : ((size_t)(A_TOT + L_TOT + node) * 64);
        op = dout + off;
    } else {
        op = g_out1 + (size_t)node * 64;
    }
    *(float2*)(op + 2 * lane) = res;
}

// ---------------------------------------------------------------------------
__global__ __launch_bounds__(256)
void bn_stats_kernel() {
    __shared__ float sh[512];
    int tid = threadIdx.x;
    int j = tid & 63;
    float s = 0.0f, s2 = 0.0f;
    for (int row = blockIdx.x * 4 + (tid >> 6); row < N_TOT; row += gridDim.x * 4) {
        float v = g_out1[(size_t)row * 64 + j];
        s += v; s2 += v * v;
    }
    sh[tid] = s; sh[256 + tid] = s2;
    __syncthreads();
    if (tid < 64) {
        float t = sh[tid] + sh[tid + 64] + sh[tid + 128] + sh[tid + 192];
        atomicAdd(&g_stats[tid], t);
    } else if (tid < 128) {
        int jj = tid - 64;
        float t = sh[256 + jj] + sh[256 + jj + 64] + sh[256 + jj + 128] + sh[256 + jj + 192];
        atomicAdd(&g_stats[64 + jj], t);
    }
}

__global__ void bn_final_kernel(const float* __restrict__ gamma, const float* __restrict__ beta) {
    int j = threadIdx.x;
    if (j >= 64) return;
    float mean = g_stats[j] * (1.0f / N_TOT);
    float var  = g_stats[64 + j] * (1.0f / N_TOT) - mean * mean;
    float rs   = rsqrtf(var + BN_EPS);
    float sc   = rs * gamma[j];
    g_stats[128 + j] = sc;
    g_stats[192 + j] = beta[j] - mean * sc;
}

// ---------------------------------------------------------------------------
extern "C" void kernel_launch(void* const* d_in, const int* in_sizes, int n_in,
                              void* d_out, int out_size) {
    const float* agent_hist = (const float*)d_in[0];
    const float* lane_nodes = (const float*)d_in[1];
    const int*   eaa        = (const int*)d_in[2];
    const float* len_aa     = (const float*)d_in[3];
    const int*   eal        = (const int*)d_in[4];
    const float* len_al     = (const float*)d_in[5];
    const float* Wih_a      = (const float*)d_in[6];
    const float* Whh_a      = (const float*)d_in[7];
    const float* b_a        = (const float*)d_in[8];
    const float* Wih_l      = (const float*)d_in[9];
    const float* Whh_l      = (const float*)d_in[10];
    const float* b_l        = (const float*)d_in[11];
    const float* w_e        = (const float*)d_in[12];
    const float* b_e        = (const float*)d_in[13];
    const float* W1         = (const float*)d_in[14];
    const float* b1         = (const float*)d_in[15];
    const float* gamma1     = (const float*)d_in[16];
    const float* beta1      = (const float*)d_in[17];
    const float* W2         = (const float*)d_in[18];
    const float* b2         = (const float*)d_in[19];
    float* out = (float*)d_out;

    const int* aa_src = eaa;
    const int* aa_dst = eaa + E_AA;
    const int* al_a   = eal;
    const int* al_l   = eal + E_AL;

    cudaFuncSetAttribute((const void*)lstm_mma_kernel<20, 5, false>,
                         cudaFuncAttributeMaxDynamicSharedMemorySize, LSTM_SMEM);
    cudaFuncSetAttribute((const void*)lstm_mma_kernel<10, 2, true>,
                         cudaFuncAttributeMaxDynamicSharedMemorySize, LSTM_SMEM);

    // agent LSTM at launch index 3 (ncu target)
    init_kernel<<<(N_TOT + 255) / 256, 256>>>();
    hist_kernel<<<(ETOT + 255) / 256, 256>>>(aa_src, aa_dst, len_aa, al_a, al_l, len_al, w_e, b_e);
    scan_kernel<<<1, 1024>>>();

    lstm_mma_kernel<20, 5, false><<<(A_TOT + 63) / 64, 512, LSTM_SMEM>>>(
        agent_hist, Wih_a, Whh_a, b_a, out, 0, A_TOT);
    lstm_mma_kernel<10, 2, true><<<(L_TOT + 63) / 64, 512, LSTM_SMEM>>>(
        lane_nodes, Wih_l, Whh_l, b_l, out + (size_t)2 * A_TOT * 64, A_TOT, L_TOT);

    dinv_kernel<<<(N_TOT + 255) / 256, 256>>>();
    scatter_kernel<<<(ETOT + 255) / 256, 256>>>(aa_src, aa_dst, len_aa, al_a, al_l, len_al, w_e, b_e);

    // conv1
    lin_kernel<<<(N_TOT + 63) / 64, 256>>>(W1, 0, 0);
    agg_csr_kernel<<<(N_TOT + 7) / 8, 256>>>(b1, out, 0);

    // BN
    bn_stats_kernel<<<512, 256>>>();
    bn_final_kernel<<<1, 64>>>(gamma1, beta1);

    // conv2
    lin_kernel<<<(N_TOT + 63) / 64, 256>>>(W2, 1, 1);
    agg_csr_kernel<<<(N_TOT + 7) / 8, 256>>>(b2, out, 1);
}

// round 10
// speedup vs baseline: 2.3054x; 1.0075x over previous
#include <cuda_runtime.h>
#include <cuda_bf16.h>
#include <cstdint>

// ---------------------------------------------------------------------------
// Problem constants
// ---------------------------------------------------------------------------
#define A_TOT 20000
#define L_TOT 80000
#define N_TOT 100000
#define E_AA  400000
#define E_AL  800000
#define ETOT  (E_AA + 2 * E_AL)
#define HDIM  64
#define BN_EPS 1e-5f

typedef unsigned long long u64;

// ---------------------------------------------------------------------------
// Scratch (device globals)
// ---------------------------------------------------------------------------
__device__ float g_x[N_TOT * HDIM];
__device__ float g_h[N_TOT * HDIM];
__device__ float g_out1[N_TOT * HDIM];
__device__ float g_deg[N_TOT];
__device__ float g_dinv[N_TOT];
__device__ float g_stats[256];
__device__ int   g_cnt[N_TOT];
__device__ int   g_rowptr[N_TOT + 1];
__device__ int   g_cursor[N_TOT];
__device__ int2  g_epack[ETOT];

// ---------------------------------------------------------------------------
// math helpers
// ---------------------------------------------------------------------------
__device__ __forceinline__ float sigmoidf_(float x) {
    return 1.0f / (1.0f + __expf(-x));
}
__device__ __forceinline__ float tanh_fast(float x) {
    float y;
    asm("tanh.approx.f32 %0, %1;" : "=f"(y) : "f"(x));
    return y;
}
__device__ __forceinline__ float sig_fast(float x) {
    return fmaf(0.5f, tanh_fast(0.5f * x), 0.5f);
}
__device__ __forceinline__ void mma_bf16(float* d, const uint32_t* a,
                                         uint32_t b0, uint32_t b1) {
    asm volatile(
        "mma.sync.aligned.m16n8k16.row.col.f32.bf16.bf16.f32 "
        "{%0,%1,%2,%3}, {%4,%5,%6,%7}, {%8,%9}, {%0,%1,%2,%3};"
        : "+f"(d[0]), "+f"(d[1]), "+f"(d[2]), "+f"(d[3])
        : "r"(a[0]), "r"(a[1]), "r"(a[2]), "r"(a[3]), "r"(b0), "r"(b1));
}
#define LDSM4(r, addr)                                                        \
    asm volatile("ldmatrix.sync.aligned.m8n8.x4.shared.b16 {%0,%1,%2,%3}, [%4];" \
        : "=r"((r)[0]), "=r"((r)[1]), "=r"((r)[2]), "=r"((r)[3]) : "r"(addr))
#define BAR_GRP(id)                                                           \
    asm volatile("bar.sync %0, 256;" :: "r"(id) : "memory")

__device__ __forceinline__ uint32_t smem_u32(const void* p) {
    uint32_t a;
    asm("{ .reg .u64 t; cvta.to.shared.u64 t, %1; cvt.u32.u64 %0, t; }"
        : "=r"(a) : "l"(p));
    return a;
}
__device__ __forceinline__ uint32_t pack_bf2(float a, float b) {
    __nv_bfloat16 ha = __float2bfloat16(a), hb = __float2bfloat16(b);
    return (uint32_t)__bfloat16_as_ushort(ha) |
           ((uint32_t)__bfloat16_as_ushort(hb) << 16);
}
__device__ __forceinline__ float bf_lo(uint32_t v) {
    return __bfloat162float(__ushort_as_bfloat16((unsigned short)(v & 0xFFFF)));
}
__device__ __forceinline__ float bf_hi(uint32_t v) {
    return __bfloat162float(__ushort_as_bfloat16((unsigned short)(v >> 16)));
}

// ---------------------------------------------------------------------------
// LSTM via mma.sync bf16, deduped B, ldmatrix, GROUP-scoped barriers.
//   A [64 rows][K=144] bf16: [h_hi(64) | h_lo(64) | x(16)]   stride 304 B
//   B [256 cols][K=144] bf16: [W_hi(64) | W_lo(64) | Xblk(16)] stride 304 B
//   All A traffic of a warp stays in its wm 32-row slice -> the two in-loop
//   barriers are bar.sync (1+wm), 256 : wm groups drift, epilogue MUFU of
//   one group overlaps mainloop HMMA of the other.
// ---------------------------------------------------------------------------
#define BSTR 304
#define SM_B_OFF (64 * BSTR)
#define LSTM_SMEM (64 * BSTR + 256 * BSTR)   // 97,280 B

template <int T, int D, bool MEAN>
__global__ __launch_bounds__(512, 2)
void lstm_mma_kernel(const float* __restrict__ xin,
                     const float* __restrict__ Wih,
                     const float* __restrict__ Whh,
                     const float* __restrict__ bias,
                     float* __restrict__ emb_out,
                     int xnode_off, int nrows)
{
    constexpr int TD = T * D;
    extern __shared__ char smem[];
    uint32_t* Aw = (uint32_t*)smem;
    const uint32_t sb = smem_u32(smem);

    const int tid  = threadIdx.x;
    const int wid  = tid >> 5, lane = tid & 31;
    const int lrow = lane >> 2, q = lane & 3;
    const int wm = wid >> 3, wn = wid & 7;   // 2m x 8n warp grid
    const int base = blockIdx.x * 64;

    // ---- zero A + B ----
    for (int i = tid; i < (64 + 256) * (BSTR / 4); i += 512) Aw[i] = 0;
    __syncthreads();

    // ---- fill B: W_hi (k0-63), W_lo (k64-127) ----
    for (int idx = tid; idx < 256 * 64; idx += 512) {
        int j = idx >> 6, k = idx & 63;
        int g = j >> 6, u = j & 63;
        int n = ((u >> 3) << 5) + (g << 3) + (u & 7);
        float w = Whh[idx];
        __nv_bfloat16 hi = __float2bfloat16(w);
        __nv_bfloat16 lo = __float2bfloat16(w - __bfloat162float(hi));
        char* bp = smem + SM_B_OFF + n * BSTR;
        *(__nv_bfloat16*)(bp + 2 * k)       = hi;
        *(__nv_bfloat16*)(bp + 128 + 2 * k) = lo;
    }
    // X block (k128-143): [Wih_hi | Wih_hi | Wih_lo | bias]
    if (tid < 256) {
        int j = tid;
        int g = j >> 6, u = j & 63;
        int n = ((u >> 3) << 5) + (g << 3) + (u & 7);
        char* bp = smem + SM_B_OFF + n * BSTR + 256;
#pragma unroll
        for (int d = 0; d < D; ++d) {
            float w = Wih[j * D + d];
            __nv_bfloat16 hi = __float2bfloat16(w);
            __nv_bfloat16 lo = __float2bfloat16(w - __bfloat162float(hi));
            *(__nv_bfloat16*)(bp + 2 * d)           = hi;
            *(__nv_bfloat16*)(bp + 2 * (D + d))     = hi;
            *(__nv_bfloat16*)(bp + 2 * (2 * D + d)) = lo;
        }
        *(__nv_bfloat16*)(bp + 2 * (3 * D)) = __float2bfloat16(bias[j]);
    }
    // A x block for t=0: [x_hi | x_lo | x_hi | 1]
    if (tid < 64) {
        *(__nv_bfloat16*)(smem + tid * BSTR + 256 + 2 * (3 * D)) = __float2bfloat16(1.0f);
    }
    if (tid < 192) {
        int r = tid & 63, part = tid >> 6;
        char* ap = smem + r * BSTR + 256;
        bool ok = (base + r < nrows);
        const float* xr = xin + (size_t)(base + r) * TD;
#pragma unroll
        for (int d = 0; d < D; ++d) {
            float v = ok ? xr[d] : 0.0f;
            __nv_bfloat16 hi = __float2bfloat16(v);
            if (part == 0)      *(__nv_bfloat16*)(ap + 2 * d) = hi;
            else if (part == 1) *(__nv_bfloat16*)(ap + 2 * (D + d)) =
                                    __float2bfloat16(v - __bfloat162float(hi));
            else                *(__nv_bfloat16*)(ap + 2 * (2 * D + d)) = hi;
        }
    }
    __syncthreads();

    // ldmatrix lane base addresses (rows confined to this warp's wm slice)
    const uint32_t aAddr0 = sb + (uint32_t)(wm * 32 + (lane & 15)) * BSTR
                          + (uint32_t)((lane >> 4) * 8) * 2;
    const uint32_t bAddr0 = sb + SM_B_OFF
                          + (uint32_t)(wn * 32 + (lane >> 4) * 8 + (lane & 7)) * BSTR
                          + (uint32_t)(((lane >> 3) & 1)) * 16;

    const int gl = tid & 255;        // group-local tid
    const int xpart = gl >> 5;       // 0..7; parts 0..2 do x-fill
    const int xrow  = wm * 32 + (gl & 31);

    float cst[8], outv[8];
#pragma unroll
    for (int i = 0; i < 8; ++i) { cst[i] = 0.0f; outv[i] = 0.0f; }

#pragma unroll 1
    for (int t = 0; t < T; ++t) {
        float acc[2][4][4];
#pragma unroll
        for (int mt = 0; mt < 2; ++mt)
#pragma unroll
            for (int nt = 0; nt < 4; ++nt)
#pragma unroll
                for (int i = 0; i < 4; ++i) acc[mt][nt][i] = 0.0f;

        if (t > 0) {
#pragma unroll 1
            for (int p = 0; p < 3; ++p) {
                const uint32_t aK2 = (p == 1) ? 128u : 0u;   // h_lo at byte 128
                const uint32_t bK2 = (p == 2) ? 128u : 0u;   // W_lo at byte 128
#pragma unroll
                for (int ks = 0; ks < 4; ++ks) {
                    uint32_t ka = aK2 + ks * 32, kb = bK2 + ks * 32;
                    uint32_t a0[4], a1[4], q0[4], q1[4];
                    LDSM4(a0, aAddr0 + ka);
                    LDSM4(a1, aAddr0 + 16 * BSTR + ka);
                    LDSM4(q0, bAddr0 + kb);
                    LDSM4(q1, bAddr0 + 16 * BSTR + kb);
                    mma_bf16(acc[0][0], a0, q0[0], q0[1]);
                    mma_bf16(acc[0][1], a0, q0[2], q0[3]);
                    mma_bf16(acc[0][2], a0, q1[0], q1[1]);
                    mma_bf16(acc[0][3], a0, q1[2], q1[3]);
                    mma_bf16(acc[1][0], a1, q0[0], q0[1]);
                    mma_bf16(acc[1][1], a1, q0[2], q0[3]);
                    mma_bf16(acc[1][2], a1, q1[0], q1[1]);
                    mma_bf16(acc[1][3], a1, q1[2], q1[3]);
                }
            }
        }
        // x pass (k bytes 256)
        {
            uint32_t a0[4], a1[4], q0[4], q1[4];
            LDSM4(a0, aAddr0 + 256);
            LDSM4(a1, aAddr0 + 16 * BSTR + 256);
            LDSM4(q0, bAddr0 + 256);
            LDSM4(q1, bAddr0 + 16 * BSTR + 256);
            mma_bf16(acc[0][0], a0, q0[0], q0[1]);
            mma_bf16(acc[0][1], a0, q0[2], q0[3]);
            mma_bf16(acc[0][2], a0, q1[0], q1[1]);
            mma_bf16(acc[0][3], a0, q1[2], q1[3]);
            mma_bf16(acc[1][0], a1, q0[0], q0[1]);
            mma_bf16(acc[1][1], a1, q0[2], q0[3]);
            mma_bf16(acc[1][2], a1, q1[0], q1[1]);
            mma_bf16(acc[1][3], a1, q1[2], q1[3]);
        }
        BAR_GRP(1 + wm);   // group's A reads done

        // epilogue (writes h in own wm slice)
#pragma unroll
        for (int mt = 0; mt < 2; ++mt)
#pragma unroll
            for (int half = 0; half < 2; ++half) {
                float hpair[2];
#pragma unroll
                for (int jp = 0; jp < 2; ++jp) {
                    int rg = half * 2 + jp;
                    float gi = acc[mt][0][rg];
                    float gf = acc[mt][1][rg];
                    float gg = acc[mt][2][rg];
                    float go = acc[mt][3][rg];
                    int ci = mt * 4 + half * 2 + jp;
                    float cn = fmaf(sig_fast(gf), cst[ci],
                                    sig_fast(gi) * tanh_fast(gg));
                    cst[ci] = cn;
                    float h = sig_fast(go) * tanh_fast(cn);
                    if (MEAN) outv[ci] += h;
                    hpair[jp] = h;
                }
                __nv_bfloat16 h0 = __float2bfloat16(hpair[0]);
                __nv_bfloat16 h1 = __float2bfloat16(hpair[1]);
                uint32_t hi2 = (uint32_t)__bfloat16_as_ushort(h0) |
                               ((uint32_t)__bfloat16_as_ushort(h1) << 16);
                uint32_t lo2 = pack_bf2(hpair[0] - __bfloat162float(h0),
                                        hpair[1] - __bfloat162float(h1));
                int row = wm * 32 + mt * 16 + half * 8 + lrow;
                int uw  = wn * 4 + q;
                Aw[row * (BSTR / 4) + uw]      = hi2;   // h_hi
                Aw[row * (BSTR / 4) + 32 + uw] = lo2;   // h_lo
            }

        // fill A_x for t+1 (group fills ONLY its own wm rows)
        if (t + 1 < T && xpart < 3) {
            char* ap = smem + xrow * BSTR + 256;
            bool ok = (base + xrow < nrows);
            const float* xr = xin + (size_t)(base + xrow) * TD + (t + 1) * D;
#pragma unroll
            for (int d = 0; d < D; ++d) {
                float v = ok ? xr[d] : 0.0f;
                __nv_bfloat16 hi = __float2bfloat16(v);
                if (xpart == 0)      *(__nv_bfloat16*)(ap + 2 * d) = hi;
                else if (xpart == 1) *(__nv_bfloat16*)(ap + 2 * (D + d)) =
                                         __float2bfloat16(v - __bfloat162float(hi));
                else                 *(__nv_bfloat16*)(ap + 2 * (2 * D + d)) = hi;
            }
        }
        BAR_GRP(1 + wm);   // group's A writes visible
    }

    // outputs
    const float scale = MEAN ? (1.0f / T) : 1.0f;
#pragma unroll
    for (int mt = 0; mt < 2; ++mt)
#pragma unroll
        for (int half = 0; half < 2; ++half) {
            int row = wm * 32 + mt * 16 + half * 8 + lrow;
            int grow = base + row;
            if (grow >= nrows) continue;
            int unit0 = wn * 8 + 2 * q;
            float2 v;
            if (MEAN) {
                int ci0 = mt * 4 + half * 2;
                v = make_float2(outv[ci0] * scale, outv[ci0 + 1] * scale);
            } else {
                uint32_t hi2 = Aw[row * (BSTR / 4) + wn * 4 + q];
                uint32_t lo2 = Aw[row * (BSTR / 4) + 32 + wn * 4 + q];
                v = make_float2(bf_lo(hi2) + bf_lo(lo2), bf_hi(hi2) + bf_hi(lo2));
            }
            *(float2*)&emb_out[(size_t)grow * 64 + unit0] = v;
            *(float2*)&g_x[(size_t)(xnode_off + grow) * 64 + unit0] = v;
        }
}

// ---------------------------------------------------------------------------
// edge decode + CSR build
// ---------------------------------------------------------------------------
__device__ __forceinline__ void edge_decode(
    int e,
    const int* __restrict__ aa_src, const int* __restrict__ aa_dst,
    const float* __restrict__ len_aa,
    const int* __restrict__ al_a, const int* __restrict__ al_l,
    const float* __restrict__ len_al,
    int& src, int& dst, float& len)
{
    if (e < E_AA) {
        src = aa_src[e]; dst = aa_dst[e]; len = len_aa[e];
    } else if (e < E_AA + E_AL) {
        int i = e - E_AA;
        src = al_a[i]; dst = A_TOT + al_l[i]; len = len_al[i];
    } else {
        int i = e - E_AA - E_AL;
        src = A_TOT + al_l[i]; dst = al_a[i]; len = len_al[i];
    }
}

__global__ void init_kernel() {
    int i = blockIdx.x * blockDim.x + threadIdx.x;
    if (i < N_TOT) { g_deg[i] = 1.0f; g_cnt[i] = 0; }
    if (i < 256) g_stats[i] = 0.0f;
}

__global__ void hist_kernel(const int* __restrict__ aa_src, const int* __restrict__ aa_dst,
                            const float* __restrict__ len_aa,
                            const int* __restrict__ al_a, const int* __restrict__ al_l,
                            const float* __restrict__ len_al,
                            const float* __restrict__ w_e, const float* __restrict__ b_e) {
    int e = blockIdx.x * blockDim.x + threadIdx.x;
    if (e >= ETOT) return;
    int src, dst; float len;
    edge_decode(e, aa_src, aa_dst, len_aa, al_a, al_l, len_al, src, dst, len);
    float w = sigmoidf_(fmaf(len, w_e[0], b_e[0]));
    atomicAdd(&g_deg[dst], w);
    atomicAdd(&g_cnt[dst], 1);
}

__global__ __launch_bounds__(1024)
void scan_kernel() {
    __shared__ int ssum[1024];
    const int C = (N_TOT + 1023) / 1024;
    int t = threadIdx.x;
    int beg = t * C, end = min(beg + C, N_TOT);
    int s = 0;
    for (int i = beg; i < end; ++i) s += g_cnt[i];
    ssum[t] = s;
    __syncthreads();
    for (int off = 1; off < 1024; off <<= 1) {
        int v = (t >= off) ? ssum[t - off] : 0;
        __syncthreads();
        ssum[t] += v;
        __syncthreads();
    }
    int run = ssum[t] - s;
    for (int i = beg; i < end; ++i) {
        g_rowptr[i] = run;
        g_cursor[i] = run;
        run += g_cnt[i];
    }
    if (t == 1023) g_rowptr[N_TOT] = ETOT;
}

__global__ void dinv_kernel() {
    int i = blockIdx.x * blockDim.x + threadIdx.x;
    if (i >= N_TOT) return;
    float d = g_deg[i];
    g_dinv[i] = (d > 0.0f) ? rsqrtf(d) : 0.0f;
}

__global__ void scatter_kernel(const int* __restrict__ aa_src, const int* __restrict__ aa_dst,
                               const float* __restrict__ len_aa,
                               const int* __restrict__ al_a, const int* __restrict__ al_l,
                               const float* __restrict__ len_al,
                               const float* __restrict__ w_e, const float* __restrict__ b_e) {
    int e = blockIdx.x * blockDim.x + threadIdx.x;
    if (e >= ETOT) return;
    int src, dst; float len;
    edge_decode(e, aa_src, aa_dst, len_aa, al_a, al_l, len_al, src, dst, len);
    float w = sigmoidf_(fmaf(len, w_e[0], b_e[0]));
    float nrm = g_dinv[src] * w * g_dinv[dst];
    int pos = atomicAdd(&g_cursor[dst], 1);
    g_epack[pos] = make_int2(src, __float_as_int(nrm));
}

// ---------------------------------------------------------------------------
__global__ __launch_bounds__(256)
void lin_kernel(const float* __restrict__ W, int in_sel, int use_bn) {
    __shared__ float Ws[64 * 65];
    __shared__ float xsh[64 * 65];
    const float* in = in_sel ? g_out1 : g_x;

    int tid = threadIdx.x;
    for (int idx = tid; idx < 64 * 64; idx += 256) {
        int k = idx >> 6, j = idx & 63;
        Ws[k * 65 + j] = W[idx];
    }
    int base = blockIdx.x * 64;
    for (int idx = tid; idx < 64 * 64; idx += 256) {
        int r = idx >> 6, k = idx & 63;
        int row = base + r;
        float v = (row < N_TOT) ? in[(size_t)row * 64 + k] : 0.0f;
        if (use_bn) v = fmaxf(fmaf(v, g_stats[128 + k], g_stats[192 + k]), 0.0f);
        xsh[r * 65 + k] = v;
    }
    __syncthreads();

    int j = tid & 63, rl = tid >> 6;
    for (int rr = rl; rr < 64; rr += 4) {
        float a = 0.0f;
#pragma unroll
        for (int k = 0; k < 64; ++k) a = fmaf(xsh[rr * 65 + k], Ws[k * 65 + j], a);
        int row = base + rr;
        if (row < N_TOT) g_h[(size_t)row * 64 + j] = a;
    }
}

// ---------------------------------------------------------------------------
// CSR aggregation, unroll-4 for MLP
// ---------------------------------------------------------------------------
__global__ __launch_bounds__(256)
void agg_csr_kernel(const float* __restrict__ bvec, float* __restrict__ dout, int map) {
    int node = blockIdx.x * 8 + (threadIdx.x >> 5);
    if (node >= N_TOT) return;
    int lane = threadIdx.x & 31;

    int beg = g_rowptr[node], end = g_rowptr[node + 1];

    float ax = 0.0f, ay = 0.0f;
    int e = beg;
    for (; e + 3 < end; e += 4) {
        int2 p0 = g_epack[e];
        int2 p1 = g_epack[e + 1];
        int2 p2 = g_epack[e + 2];
        int2 p3 = g_epack[e + 3];
        float2 v0 = *(const float2*)&g_h[(size_t)p0.x * 64 + 2 * lane];
        float2 v1 = *(const float2*)&g_h[(size_t)p1.x * 64 + 2 * lane];
        float2 v2 = *(const float2*)&g_h[(size_t)p2.x * 64 + 2 * lane];
        float2 v3 = *(const float2*)&g_h[(size_t)p3.x * 64 + 2 * lane];
        float n0 = __int_as_float(p0.y), n1 = __int_as_float(p1.y);
        float n2 = __int_as_float(p2.y), n3 = __int_as_float(p3.y);
        ax = fmaf(v0.x, n0, ax); ay = fmaf(v0.y, n0, ay);
        ax = fmaf(v1.x, n1, ax); ay = fmaf(v1.y, n1, ay);
        ax = fmaf(v2.x, n2, ax); ay = fmaf(v2.y, n2, ay);
        ax = fmaf(v3.x, n3, ax); ay = fmaf(v3.y, n3, ay);
    }
    for (; e < end; ++e) {
        int2 p0 = g_epack[e];
        float2 v0 = *(const float2*)&g_h[(size_t)p0.x * 64 + 2 * lane];
        float n0 = __int_as_float(p0.y);
        ax = fmaf(v0.x, n0, ax); ay = fmaf(v0.y, n0, ay);
    }

    float di = g_dinv[node];
    float dd = di * di;
    float2 hv = *(const float2*)&g_h[(size_t)node * 64 + 2 * lane];
    float2 bv = *(const float2*)&bvec[2 * lane];
    float2 res;
    res.x = fmaf(hv.x, dd, ax) + bv.x;
    res.y = fmaf(hv.y, dd, ay) + bv.y;

    float* op;
    if (map) {
        size_t off = (node < A_TOT) ? ((size_t)(A_TOT + node) * 64)
                                    : ((size_t)(A_TOT + L_TOT + node) * 64);
        op = dout + off;
    } else {
        op = g_out1 + (size_t)node * 64;
    }
    *(float2*)(op + 2 * lane) = res;
}

// ---------------------------------------------------------------------------
__global__ __launch_bounds__(256)
void bn_stats_kernel() {
    __shared__ float sh[512];
    int tid = threadIdx.x;
    int j = tid & 63;
    float s = 0.0f, s2 = 0.0f;
    for (int row = blockIdx.x * 4 + (tid >> 6); row < N_TOT; row += gridDim.x * 4) {
        float v = g_out1[(size_t)row * 64 + j];
        s += v; s2 += v * v;
    }
    sh[tid] = s; sh[256 + tid] = s2;
    __syncthreads();
    if (tid < 64) {
        float t = sh[tid] + sh[tid + 64] + sh[tid + 128] + sh[tid + 192];
        atomicAdd(&g_stats[tid], t);
    } else if (tid < 128) {
        int jj = tid - 64;
        float t = sh[256 + jj] + sh[256 + jj + 64] + sh[256 + jj + 128] + sh[256 + jj + 192];
        atomicAdd(&g_stats[64 + jj], t);
    }
}

__global__ void bn_final_kernel(const float* __restrict__ gamma, const float* __restrict__ beta) {
    int j = threadIdx.x;
    if (j >= 64) return;
    float mean = g_stats[j] * (1.0f / N_TOT);
    float var  = g_stats[64 + j] * (1.0f / N_TOT) - mean * mean;
    float rs   = rsqrtf(var + BN_EPS);
    float sc   = rs * gamma[j];
    g_stats[128 + j] = sc;
    g_stats[192 + j] = beta[j] - mean * sc;
}

// ---------------------------------------------------------------------------
extern "C" void kernel_launch(void* const* d_in, const int* in_sizes, int n_in,
                              void* d_out, int out_size) {
    const float* agent_hist = (const float*)d_in[0];
    const float* lane_nodes = (const float*)d_in[1];
    const int*   eaa        = (const int*)d_in[2];
    const float* len_aa     = (const float*)d_in[3];
    const int*   eal        = (const int*)d_in[4];
    const float* len_al     = (const float*)d_in[5];
    const float* Wih_a      = (const float*)d_in[6];
    const float* Whh_a      = (const float*)d_in[7];
    const float* b_a        = (const float*)d_in[8];
    const float* Wih_l      = (const float*)d_in[9];
    const float* Whh_l      = (const float*)d_in[10];
    const float* b_l        = (const float*)d_in[11];
    const float* w_e        = (const float*)d_in[12];
    const float* b_e        = (const float*)d_in[13];
    const float* W1         = (const float*)d_in[14];
    const float* b1         = (const float*)d_in[15];
    const float* gamma1     = (const float*)d_in[16];
    const float* beta1      = (const float*)d_in[17];
    const float* W2         = (const float*)d_in[18];
    const float* b2         = (const float*)d_in[19];
    float* out = (float*)d_out;

    const int* aa_src = eaa;
    const int* aa_dst = eaa + E_AA;
    const int* al_a   = eal;
    const int* al_l   = eal + E_AL;

    cudaFuncSetAttribute((const void*)lstm_mma_kernel<20, 5, false>,
                         cudaFuncAttributeMaxDynamicSharedMemorySize, LSTM_SMEM);
    cudaFuncSetAttribute((const void*)lstm_mma_kernel<10, 2, true>,
                         cudaFuncAttributeMaxDynamicSharedMemorySize, LSTM_SMEM);

    // agent LSTM at launch index 3 (ncu target)
    init_kernel<<<(N_TOT + 255) / 256, 256>>>();
    hist_kernel<<<(ETOT + 255) / 256, 256>>>(aa_src, aa_dst, len_aa, al_a, al_l, len_al, w_e, b_e);
    scan_kernel<<<1, 1024>>>();

    lstm_mma_kernel<20, 5, false><<<(A_TOT + 63) / 64, 512, LSTM_SMEM>>>(
        agent_hist, Wih_a, Whh_a, b_a, out, 0, A_TOT);
    lstm_mma_kernel<10, 2, true><<<(L_TOT + 63) / 64, 512, LSTM_SMEM>>>(
        lane_nodes, Wih_l, Whh_l, b_l, out + (size_t)2 * A_TOT * 64, A_TOT, L_TOT);

    dinv_kernel<<<(N_TOT + 255) / 256, 256>>>();
    scatter_kernel<<<(ETOT + 255) / 256, 256>>>(aa_src, aa_dst, len_aa, al_a, al_l, len_al, w_e, b_e);

    // conv1
    lin_kernel<<<(N_TOT + 63) / 64, 256>>>(W1, 0, 0);
    agg_csr_kernel<<<(N_TOT + 7) / 8, 256>>>(b1, out, 0);

    // BN
    bn_stats_kernel<<<512, 256>>>();
    bn_final_kernel<<<1, 64>>>(gamma1, beta1);

    // conv2
    lin_kernel<<<(N_TOT + 63) / 64, 256>>>(W2, 1, 1);
    agg_csr_kernel<<<(N_TOT + 7) / 8, 256>>>(b2, out, 1);
}